// round 6
// baseline (speedup 1.0000x reference)
#include <cuda_runtime.h>
#include <cuda_bf16.h>
#include <math.h>
#include <stdint.h>

#define TOK   16384
#define Dm    512
#define Tt    4096
#define Bb    4
#define Hh    8
#define HDm   64
#define Lnum  6
#define MLPD  2048

#define WSZP  (Dm*Dm)
#define WSZM  (Dm*MLPD)
#define SZ_QKV (3*WSZP)
#define OFF_QKV 0
#define OFF_WO (6*SZ_QKV)
#define OFF_W1 (OFF_WO + 6*WSZP)
#define OFF_W2 (OFF_W1 + 6*WSZM)
#define WTOT   (OFF_W2 + 6*WSZM)

// ---------------- scratch (device globals) ----------------
__device__ __align__(128) float g_x[TOK * Dm];
__device__ __align__(128) float g_qkv[TOK * 3 * Dm];
__device__ __align__(128) __nv_bfloat16 g_hhi[TOK * Dm];
__device__ __align__(128) __nv_bfloat16 g_hlo[TOK * Dm];
__device__ __align__(128) __nv_bfloat16 g_ahi[TOK * Dm];
__device__ __align__(128) __nv_bfloat16 g_alo[TOK * Dm];
__device__ __align__(128) __nv_bfloat16 g_mhi[(size_t)TOK * MLPD];
__device__ __align__(128) __nv_bfloat16 g_mlo[(size_t)TOK * MLPD];
__device__ __align__(128) __nv_bfloat16 g_whi[WTOT];
__device__ __align__(128) __nv_bfloat16 g_wlo[WTOT];

// ---------------- helpers ----------------
__device__ __forceinline__ uint32_t smem_u32(const void* p) {
    uint32_t a;
    asm("{ .reg .u64 t; cvta.to.shared.u64 t, %1; cvt.u32.u64 %0, t; }" : "=r"(a) : "l"(p));
    return a;
}
#define SWZ(o) ((o) ^ (((o) >> 3) & 0x70))

#define CP16(dst, src) \
    asm volatile("cp.async.cg.shared.global [%0], [%1], 16;" :: "r"(dst), "l"(src) : "memory")
#define CP_COMMIT() asm volatile("cp.async.commit_group;" ::: "memory")
#define CP_WAIT(n)  asm volatile("cp.async.wait_group %0;" :: "n"(n) : "memory")

__device__ __forceinline__ void ldsm4(uint32_t* r, uint32_t a) {
    asm volatile("ldmatrix.sync.aligned.m8n8.x4.shared.b16 {%0,%1,%2,%3}, [%4];"
                 : "=r"(r[0]), "=r"(r[1]), "=r"(r[2]), "=r"(r[3]) : "r"(a));
}
__device__ __forceinline__ void mma16816(float* c, const uint32_t* a,
                                         uint32_t b0, uint32_t b1) {
    asm volatile("mma.sync.aligned.m16n8k16.row.col.f32.bf16.bf16.f32 "
                 "{%0,%1,%2,%3},{%4,%5,%6,%7},{%8,%9},{%0,%1,%2,%3};"
                 : "+f"(c[0]), "+f"(c[1]), "+f"(c[2]), "+f"(c[3])
                 : "r"(a[0]), "r"(a[1]), "r"(a[2]), "r"(a[3]), "r"(b0), "r"(b1));
}
__device__ __forceinline__ void bfsplit(float x, __nv_bfloat16& h, __nv_bfloat16& l) {
    h = __float2bfloat16(x);
    l = __float2bfloat16(x - __bfloat162float(h));
}

// ============================================================
// Embedding + PE
// ============================================================
__global__ void embed_kernel(const int* __restrict__ inputs,
                             const float* __restrict__ embed,
                             float* __restrict__ x) {
    size_t id = (size_t)blockIdx.x * blockDim.x + threadIdx.x;
    int token = (int)(id >> 9);
    int d = (int)(id & 511);
    int pos = token & (Tt - 1);
    int tok = inputs[token];
    int i = (d < 256) ? d : d - 256;
    const float c = (float)(-9.210340371976184 / 512.0);
    float div = expf((float)(2 * i) * c);
    float ang = (float)pos * div;
    float pe = (d < 256) ? sinf(ang) : cosf(ang);
    x[id] = embed[(size_t)tok * Dm + d] + pe;
}

// ============================================================
// Fused weight prep (one launch)
// ============================================================
__global__ void wprep_all(const float* __restrict__ wq, const float* __restrict__ wk,
                          const float* __restrict__ wv, const float* __restrict__ wo,
                          const float* __restrict__ w1, const float* __restrict__ w2,
                          __nv_bfloat16* __restrict__ hi, __nv_bfloat16* __restrict__ lo) {
    __shared__ float tt[32][33];
    int t = blockIdx.x;
    const float* src;
    __nv_bfloat16 *dh, *dl;
    int srcN, dstK, n0, k0, nd;

    if (t < 4608) {
        int g = t / 1536, r = t % 1536;
        int l = r >> 8, rr = r & 255;
        n0 = (rr & 15) << 5; k0 = (rr >> 4) << 5;
        const float* w = (g == 0) ? wq : (g == 1) ? wk : wv;
        src = w + (size_t)l * WSZP;
        dh = hi + OFF_QKV + (size_t)l * SZ_QKV;
        dl = lo + OFF_QKV + (size_t)l * SZ_QKV;
        srcN = 512; dstK = 512; nd = g * 512 + n0;
    } else if (t < 6144) {
        int r = t - 4608;
        int l = r >> 8, rr = r & 255;
        n0 = (rr & 15) << 5; k0 = (rr >> 4) << 5;
        src = wo + (size_t)l * WSZP;
        dh = hi + OFF_WO + (size_t)l * WSZP;
        dl = lo + OFF_WO + (size_t)l * WSZP;
        srcN = 512; dstK = 512; nd = n0;
    } else if (t < 12288) {
        int r = t - 6144;
        int l = r >> 10, rr = r & 1023;
        n0 = (rr & 63) << 5; k0 = (rr >> 6) << 5;
        src = w1 + (size_t)l * WSZM;
        dh = hi + OFF_W1 + (size_t)l * WSZM;
        dl = lo + OFF_W1 + (size_t)l * WSZM;
        srcN = 2048; dstK = 512; nd = n0;
    } else {
        int r = t - 12288;
        int l = r >> 10, rr = r & 1023;
        n0 = (rr & 15) << 5; k0 = (rr >> 4) << 5;
        src = w2 + (size_t)l * WSZM;
        dh = hi + OFF_W2 + (size_t)l * WSZM;
        dl = lo + OFF_W2 + (size_t)l * WSZM;
        srcN = 512; dstK = 2048; nd = n0;
    }

    int tx = threadIdx.x, ty = threadIdx.y;
#pragma unroll
    for (int i = 0; i < 4; i++)
        tt[ty + i * 8][tx] = src[(size_t)(k0 + ty + i * 8) * srcN + n0 + tx];
    __syncthreads();
#pragma unroll
    for (int i = 0; i < 4; i++) {
        float v = tt[tx][ty + i * 8];
        __nv_bfloat16 h, L;
        bfsplit(v, h, L);
        size_t o = (size_t)(nd + ty + i * 8) * dstK + k0 + tx;
        dh[o] = h;
        dl[o] = L;
    }
}

// ============================================================
// LayerNorm
// ============================================================
template <bool WBF>
__global__ void ln_kernel(const float* __restrict__ x,
                          const float* __restrict__ sc,
                          const float* __restrict__ bi,
                          float* __restrict__ outf,
                          __nv_bfloat16* __restrict__ ohi,
                          __nv_bfloat16* __restrict__ olo) {
    __shared__ float red[4];
    int t = blockIdx.x;
    const float* xr = x + (size_t)t * Dm;
    float v[4];
    float sum = 0.f;
#pragma unroll
    for (int i = 0; i < 4; i++) { v[i] = xr[threadIdx.x + i * 128]; sum += v[i]; }
#pragma unroll
    for (int o = 16; o; o >>= 1) sum += __shfl_xor_sync(0xffffffffu, sum, o);
    if ((threadIdx.x & 31) == 0) red[threadIdx.x >> 5] = sum;
    __syncthreads();
    float mean = (red[0] + red[1] + red[2] + red[3]) * (1.f / Dm);
    __syncthreads();
    float sq = 0.f;
#pragma unroll
    for (int i = 0; i < 4; i++) { float d = v[i] - mean; sq += d * d; }
#pragma unroll
    for (int o = 16; o; o >>= 1) sq += __shfl_xor_sync(0xffffffffu, sq, o);
    if ((threadIdx.x & 31) == 0) red[threadIdx.x >> 5] = sq;
    __syncthreads();
    float var = (red[0] + red[1] + red[2] + red[3]) * (1.f / Dm);
    float rstd = rsqrtf(var + 1e-6f);
#pragma unroll
    for (int i = 0; i < 4; i++) {
        int idx = threadIdx.x + i * 128;
        float y = (v[i] - mean) * rstd * sc[idx] + bi[idx];
        if (WBF) {
            __nv_bfloat16 h, L;
            bfsplit(y, h, L);
            ohi[(size_t)t * Dm + idx] = h;
            olo[(size_t)t * Dm + idx] = L;
        } else {
            outf[(size_t)t * Dm + idx] = y;
        }
    }
}

// ============================================================
// HMMA bf16 split-precision GEMM
// CTA tile 256x128, 8 warps (256 thr), warp tile 64x64,
// K-chunk 64, 2-stage cp.async (96KB/stage).
// MMA:LDSM = 6:1 (was 2:1) — tests issue/LDSM-contention hypothesis.
// ============================================================
#define ST_A_HI 0
#define ST_A_LO 32768
#define ST_B_HI 65536
#define ST_B_LO 81920
#define STAGE   98304
#define SMEM_GEMM (2 * STAGE)

template <bool ACCUM, bool RELU, bool BIAS, bool WF32, bool WBF>
__global__ void __launch_bounds__(256, 1)
hgemm(const __nv_bfloat16* __restrict__ Ahi, const __nv_bfloat16* __restrict__ Alo,
      const __nv_bfloat16* __restrict__ Bhi, const __nv_bfloat16* __restrict__ Blo,
      const float* __restrict__ bias, float* __restrict__ C,
      __nv_bfloat16* __restrict__ Ohi, __nv_bfloat16* __restrict__ Olo,
      int N, int K) {
    extern __shared__ char smem[];
    uint32_t sb = smem_u32(smem);
    int tid = threadIdx.x, wid = tid >> 5, lane = tid & 31;
    int m0 = blockIdx.y * 256, n0 = blockIdx.x * 128;
    int wm = (wid >> 1) * 64, wn = (wid & 1) * 64;

    float acc[4][8][4];
#pragma unroll
    for (int i = 0; i < 4; i++)
#pragma unroll
        for (int j = 0; j < 8; j++)
#pragma unroll
            for (int e = 0; e < 4; e++) acc[i][j][e] = 0.f;

    const int NC = K >> 6;

#define LOAD_CHUNK(c, s) do {                                                   \
    int kt = (c) << 6;                                                          \
    uint32_t st_ = sb + (s) * STAGE;                                            \
    _Pragma("unroll")                                                           \
    for (int i = 0; i < 8; i++) {   /* A: 256 rows, hi+lo */                    \
        int u = tid + i * 256;                                                  \
        int row = u >> 3, kc = u & 7;                                           \
        uint32_t so = SWZ((uint32_t)(row * 128 + kc * 16));                     \
        size_t ga = (size_t)(m0 + row) * K + kt + kc * 8;                       \
        CP16(st_ + ST_A_HI + so, Ahi + ga);                                     \
        CP16(st_ + ST_A_LO + so, Alo + ga);                                     \
    }                                                                           \
    _Pragma("unroll")                                                           \
    for (int i = 0; i < 4; i++) {   /* B: 128 rows, hi+lo */                    \
        int u = tid + i * 256;                                                  \
        int row = u >> 3, kc = u & 7;                                           \
        uint32_t so = SWZ((uint32_t)(row * 128 + kc * 16));                     \
        size_t gb = (size_t)(n0 + row) * K + kt + kc * 8;                       \
        CP16(st_ + ST_B_HI + so, Bhi + gb);                                     \
        CP16(st_ + ST_B_LO + so, Blo + gb);                                     \
    } } while (0)

    LOAD_CHUNK(0, 0);
    CP_COMMIT();
    LOAD_CHUNK(1, 1);
    CP_COMMIT();

    for (int c = 0; c < NC; c++) {
        if (c + 1 < NC) { CP_WAIT(1); } else { CP_WAIT(0); }
        __syncthreads();
        uint32_t st = sb + (c & 1) * STAGE;

#pragma unroll
        for (int ks = 0; ks < 4; ks++) {
            int kb = ks * 32 + ((lane >> 4) & 1) * 16;
            uint32_t ah[4][4], al[4][4];
#pragma unroll
            for (int mf = 0; mf < 4; mf++) {
                uint32_t ro = (uint32_t)((wm + mf * 16 + (lane & 15)) * 128 + kb);
                ldsm4(ah[mf], st + ST_A_HI + SWZ(ro));
                ldsm4(al[mf], st + ST_A_LO + SWZ(ro));
            }
#pragma unroll
            for (int nf = 0; nf < 4; nf++) {
                uint32_t bh[4], bl[4];
                uint32_t ro = (uint32_t)((wn + nf * 16 + (lane & 15)) * 128 + kb);
                ldsm4(bh, st + ST_B_HI + SWZ(ro));
                ldsm4(bl, st + ST_B_LO + SWZ(ro));
#pragma unroll
                for (int mf = 0; mf < 4; mf++)
#pragma unroll
                    for (int sl = 0; sl < 2; sl++) {
                        int nb = nf * 2 + sl;
                        mma16816(acc[mf][nb], ah[mf], bh[sl], bh[sl + 2]);
                        mma16816(acc[mf][nb], ah[mf], bl[sl], bl[sl + 2]);
                        mma16816(acc[mf][nb], al[mf], bh[sl], bh[sl + 2]);
                    }
            }
        }
        __syncthreads();
        if (c + 2 < NC) {
            LOAD_CHUNK(c + 2, c & 1);
            CP_COMMIT();
        }
    }

    // epilogue
    int r0 = m0 + wm + (lane >> 2);
    int cb = n0 + wn + (lane & 3) * 2;
#pragma unroll
    for (int mf = 0; mf < 4; mf++)
#pragma unroll
        for (int half = 0; half < 2; half++) {
            int rr = r0 + mf * 16 + half * 8;
#pragma unroll
            for (int nb = 0; nb < 8; nb++) {
                int cc = cb + nb * 8;
                float v0 = acc[mf][nb][half * 2 + 0];
                float v1 = acc[mf][nb][half * 2 + 1];
                if (BIAS) {
                    float2 bv = *(const float2*)(bias + cc);
                    v0 += bv.x; v1 += bv.y;
                }
                if (RELU) { v0 = fmaxf(v0, 0.f); v1 = fmaxf(v1, 0.f); }
                if (ACCUM) {
                    float2 o = *(const float2*)(C + (size_t)rr * N + cc);
                    v0 += o.x; v1 += o.y;
                }
                if (WF32)
                    *(float2*)(C + (size_t)rr * N + cc) = make_float2(v0, v1);
                if (WBF) {
                    __nv_bfloat16 h0, l0, h1, l1;
                    bfsplit(v0, h0, l0);
                    bfsplit(v1, h1, l1);
                    *(__nv_bfloat162*)(Ohi + (size_t)rr * N + cc) = __halves2bfloat162(h0, h1);
                    *(__nv_bfloat162*)(Olo + (size_t)rr * N + cc) = __halves2bfloat162(l0, l1);
                }
            }
        }
}

// ============================================================
// Local block attention (reads packed qkv, stride 1536)
// ============================================================
__global__ void attn_kernel(const float* __restrict__ qkv,
                            const int* __restrict__ inputs,
                            __nv_bfloat16* __restrict__ ahi,
                            __nv_bfloat16* __restrict__ alo,
                            int lp) {
    __shared__ float buf0[64 * 64];
    __shared__ float buf1[64 * 64];
    __shared__ float maskS[64];

    int n = blockIdx.x, h = blockIdx.y, b = blockIdx.z;
    int tid = threadIdx.x;
    int base = n * 64 - lp;

#pragma unroll
    for (int i = 0; i < 4; i++) {
        int t4 = tid + i * 256;
        int row = t4 >> 4, c4 = t4 & 15;
        int gt = base + row;
        float4 qv = make_float4(0.f, 0.f, 0.f, 0.f);
        float4 kv = qv;
        if (gt >= 0 && gt < Tt) {
            size_t off = ((size_t)(b * Tt + gt)) * 1536 + h * HDm;
            qv = ((const float4*)(qkv + off))[c4];
            kv = ((const float4*)(qkv + off + 512))[c4];
        }
        ((float4*)(buf0 + row * 64))[c4] = qv;
        ((float4*)(buf1 + row * 64))[c4] = kv;
    }
    if (tid < 64) {
        int gt = base + tid;
        maskS[tid] = (gt >= 0 && gt < Tt && inputs[b * Tt + gt] > 0) ? 1.f : 0.f;
    }
    __syncthreads();

    int qr = tid >> 2;
    int kc0 = (tid & 3) * 16;
    float acc[16];
#pragma unroll
    for (int j = 0; j < 16; j++) acc[j] = 0.f;
#pragma unroll
    for (int f4 = 0; f4 < 16; f4++) {
        float4 qv = ((float4*)(buf0 + qr * 64))[f4];
#pragma unroll
        for (int j = 0; j < 16; j++) {
            float4 kv = ((float4*)(buf1 + (kc0 + j) * 64))[f4];
            acc[j] += qv.x * kv.x + qv.y * kv.y + qv.z * kv.z + qv.w * kv.w;
        }
    }
    __syncthreads();

#pragma unroll
    for (int j = 0; j < 16; j++)
        buf0[qr * 64 + kc0 + j] = (maskS[kc0 + j] > 0.f) ? acc[j] * 0.125f : -1e9f;

#pragma unroll
    for (int i = 0; i < 4; i++) {
        int t4 = tid + i * 256;
        int row = t4 >> 4, c4 = t4 & 15;
        int gt = base + row;
        float4 vv = make_float4(0.f, 0.f, 0.f, 0.f);
        if (gt >= 0 && gt < Tt)
            vv = ((const float4*)(qkv + ((size_t)(b * Tt + gt)) * 1536 + h * HDm + 1024))[c4];
        ((float4*)(buf1 + row * 64))[c4] = vv;
    }
    __syncthreads();

    if (tid < 64) {
        float* row = buf0 + tid * 64;
        float m = -1e30f;
#pragma unroll 8
        for (int i2 = 0; i2 < 64; i2++) m = fmaxf(m, row[i2]);
        float s = 0.f;
#pragma unroll 8
        for (int i2 = 0; i2 < 64; i2++) { float e = expf(row[i2] - m); row[i2] = e; s += e; }
        float inv = 1.f / s;
#pragma unroll 8
        for (int i2 = 0; i2 < 64; i2++) row[i2] *= inv;
    }
    __syncthreads();

    float o[16];
#pragma unroll
    for (int j = 0; j < 16; j++) o[j] = 0.f;
    for (int kk = 0; kk < 64; kk++) {
        float p = buf0[qr * 64 + kk];
#pragma unroll
        for (int j4 = 0; j4 < 4; j4++) {
            float4 vv = ((float4*)(buf1 + kk * 64 + kc0))[j4];
            o[j4 * 4 + 0] += p * vv.x;
            o[j4 * 4 + 1] += p * vv.y;
            o[j4 * 4 + 2] += p * vv.z;
            o[j4 * 4 + 3] += p * vv.w;
        }
    }
    int gt = base + qr;
    if (gt >= 0 && gt < Tt) {
        size_t ob = ((size_t)(b * Tt + gt)) * Dm + h * HDm + kc0;
#pragma unroll
        for (int j = 0; j < 16; j += 2) {
            __nv_bfloat16 h0, l0, h1, l1;
            bfsplit(o[j], h0, l0);
            bfsplit(o[j + 1], h1, l1);
            *(__nv_bfloat162*)(ahi + ob + j) = __halves2bfloat162(h0, h1);
            *(__nv_bfloat162*)(alo + ob + j) = __halves2bfloat162(l0, l1);
        }
    }
}

// ============================================================
// Host driver
// ============================================================
extern "C" void kernel_launch(void* const* d_in, const int* in_sizes, int n_in,
                              void* d_out, int out_size) {
    const int*   inputs = (const int*)  d_in[0];
    const float* embed  = (const float*)d_in[1];
    const float* wq     = (const float*)d_in[2];
    const float* wk     = (const float*)d_in[3];
    const float* wv     = (const float*)d_in[4];
    const float* wo     = (const float*)d_in[5];
    const float* ln1_s  = (const float*)d_in[6];
    const float* ln1_b  = (const float*)d_in[7];
    const float* ln2_s  = (const float*)d_in[8];
    const float* ln2_b  = (const float*)d_in[9];
    const float* w1     = (const float*)d_in[10];
    const float* b1     = (const float*)d_in[11];
    const float* w2     = (const float*)d_in[12];
    const float* b2     = (const float*)d_in[13];
    const float* lnf_s  = (const float*)d_in[14];
    const float* lnf_b  = (const float*)d_in[15];

    float *x, *qkv;
    __nv_bfloat16 *hhi, *hlo, *ahi, *alo, *mhi, *mlo, *whi, *wlo;
    cudaGetSymbolAddress((void**)&x,   g_x);
    cudaGetSymbolAddress((void**)&qkv, g_qkv);
    cudaGetSymbolAddress((void**)&hhi, g_hhi);
    cudaGetSymbolAddress((void**)&hlo, g_hlo);
    cudaGetSymbolAddress((void**)&ahi, g_ahi);
    cudaGetSymbolAddress((void**)&alo, g_alo);
    cudaGetSymbolAddress((void**)&mhi, g_mhi);
    cudaGetSymbolAddress((void**)&mlo, g_mlo);
    cudaGetSymbolAddress((void**)&whi, g_whi);
    cudaGetSymbolAddress((void**)&wlo, g_wlo);

    cudaFuncSetAttribute(hgemm<false,false,false,true,false>, cudaFuncAttributeMaxDynamicSharedMemorySize, SMEM_GEMM);
    cudaFuncSetAttribute(hgemm<true, false,false,true,false>, cudaFuncAttributeMaxDynamicSharedMemorySize, SMEM_GEMM);
    cudaFuncSetAttribute(hgemm<false,true, true, false,true>, cudaFuncAttributeMaxDynamicSharedMemorySize, SMEM_GEMM);
    cudaFuncSetAttribute(hgemm<true, false,true, true, false>, cudaFuncAttributeMaxDynamicSharedMemorySize, SMEM_GEMM);

    wprep_all<<<18432, dim3(32, 8)>>>(wq, wk, wv, wo, w1, w2, whi, wlo);
    embed_kernel<<<(TOK * Dm) / 256, 256>>>(inputs, embed, x);

    dim3 gQKV(1536 / 128, TOK / 256);
    dim3 gP(Dm / 128, TOK / 256);
    dim3 gM1(MLPD / 128, TOK / 256);

    for (int l = 0; l < Lnum; l++) {
        int lp = (l & 1) ? 32 : 0;
        int nb = (l & 1) ? (Tt + 64) / 64 : Tt / 64;

        ln_kernel<true><<<TOK, 128>>>(x, ln1_s + l * Dm, ln1_b + l * Dm,
                                      nullptr, hhi, hlo);

        hgemm<false,false,false,true,false><<<gQKV, 256, SMEM_GEMM>>>(
            hhi, hlo,
            whi + OFF_QKV + (size_t)l * SZ_QKV, wlo + OFF_QKV + (size_t)l * SZ_QKV,
            nullptr, qkv, nullptr, nullptr, 1536, Dm);

        attn_kernel<<<dim3(nb, Hh, Bb), 256>>>(qkv, inputs, ahi, alo, lp);

        hgemm<true,false,false,true,false><<<gP, 256, SMEM_GEMM>>>(
            ahi, alo,
            whi + OFF_WO + (size_t)l * WSZP, wlo + OFF_WO + (size_t)l * WSZP,
            nullptr, x, nullptr, nullptr, Dm, Dm);

        ln_kernel<true><<<TOK, 128>>>(x, ln2_s + l * Dm, ln2_b + l * Dm,
                                      nullptr, hhi, hlo);

        hgemm<false,true,true,false,true><<<gM1, 256, SMEM_GEMM>>>(
            hhi, hlo,
            whi + OFF_W1 + (size_t)l * WSZM, wlo + OFF_W1 + (size_t)l * WSZM,
            b1 + (size_t)l * MLPD, nullptr, mhi, mlo, MLPD, Dm);

        hgemm<true,false,true,true,false><<<gP, 256, SMEM_GEMM>>>(
            mhi, mlo,
            whi + OFF_W2 + (size_t)l * WSZM, wlo + OFF_W2 + (size_t)l * WSZM,
            b2 + (size_t)l * Dm, x, nullptr, nullptr, Dm, MLPD);
    }

    ln_kernel<false><<<TOK, 128>>>(x, lnf_s, lnf_b, (float*)d_out, nullptr, nullptr);
}

// round 7
// speedup vs baseline: 1.2129x; 1.2129x over previous
#include <cuda_runtime.h>
#include <cuda_fp16.h>
#include <math.h>
#include <stdint.h>

#define TOK   16384
#define Dm    512
#define Tt    4096
#define Bb    4
#define Hh    8
#define HDm   64
#define Lnum  6
#define MLPD  2048

#define WSZP  (Dm*Dm)
#define WSZM  (Dm*MLPD)
#define SZ_QKV (3*WSZP)
#define OFF_QKV 0
#define OFF_WO (6*SZ_QKV)
#define OFF_W1 (OFF_WO + 6*WSZP)
#define OFF_W2 (OFF_W1 + 6*WSZM)
#define WTOT   (OFF_W2 + 6*WSZM)

// ---------------- scratch (device globals) ----------------
__device__ __align__(128) float g_x[TOK * Dm];
__device__ __align__(128) float g_qkv[TOK * 3 * Dm];
__device__ __align__(128) __half g_hhi[TOK * Dm];
__device__ __align__(128) __half g_hlo[TOK * Dm];
__device__ __align__(128) __half g_ahi[TOK * Dm];
__device__ __align__(128) __half g_alo[TOK * Dm];
__device__ __align__(128) __half g_mhi[(size_t)TOK * MLPD];
__device__ __align__(128) __half g_mlo[(size_t)TOK * MLPD];
__device__ __align__(128) __half g_wh[WTOT];

// ---------------- helpers ----------------
__device__ __forceinline__ uint32_t smem_u32(const void* p) {
    uint32_t a;
    asm("{ .reg .u64 t; cvta.to.shared.u64 t, %1; cvt.u32.u64 %0, t; }" : "=r"(a) : "l"(p));
    return a;
}
#define SWZ(o) ((o) ^ (((o) >> 3) & 0x70))

#define CP16(dst, src) \
    asm volatile("cp.async.cg.shared.global [%0], [%1], 16;" :: "r"(dst), "l"(src) : "memory")
#define CP_COMMIT() asm volatile("cp.async.commit_group;" ::: "memory")
#define CP_WAIT(n)  asm volatile("cp.async.wait_group %0;" :: "n"(n) : "memory")

__device__ __forceinline__ void ldsm4(uint32_t* r, uint32_t a) {
    asm volatile("ldmatrix.sync.aligned.m8n8.x4.shared.b16 {%0,%1,%2,%3}, [%4];"
                 : "=r"(r[0]), "=r"(r[1]), "=r"(r[2]), "=r"(r[3]) : "r"(a));
}
__device__ __forceinline__ void mma16816(float* c, const uint32_t* a,
                                         uint32_t b0, uint32_t b1) {
    asm volatile("mma.sync.aligned.m16n8k16.row.col.f32.f16.f16.f32 "
                 "{%0,%1,%2,%3},{%4,%5,%6,%7},{%8,%9},{%0,%1,%2,%3};"
                 : "+f"(c[0]), "+f"(c[1]), "+f"(c[2]), "+f"(c[3])
                 : "r"(a[0]), "r"(a[1]), "r"(a[2]), "r"(a[3]), "r"(b0), "r"(b1));
}
__device__ __forceinline__ void hsplit(float x, __half& h, __half& l) {
    h = __float2half_rn(x);
    l = __float2half_rn(x - __half2float(h));
}

// ============================================================
// Embedding + PE
// ============================================================
__global__ void embed_kernel(const int* __restrict__ inputs,
                             const float* __restrict__ embed,
                             float* __restrict__ x) {
    size_t id = (size_t)blockIdx.x * blockDim.x + threadIdx.x;
    int token = (int)(id >> 9);
    int d = (int)(id & 511);
    int pos = token & (Tt - 1);
    int tok = inputs[token];
    int i = (d < 256) ? d : d - 256;
    const float c = (float)(-9.210340371976184 / 512.0);
    float div = expf((float)(2 * i) * c);
    float ang = (float)pos * div;
    float pe = (d < 256) ? sinf(ang) : cosf(ang);
    x[id] = embed[(size_t)tok * Dm + d] + pe;
}

// ============================================================
// Fused weight prep (one launch): fp32 [K][N] -> fp16 [N][K]
// ============================================================
__global__ void wprep_all(const float* __restrict__ wq, const float* __restrict__ wk,
                          const float* __restrict__ wv, const float* __restrict__ wo,
                          const float* __restrict__ w1, const float* __restrict__ w2,
                          __half* __restrict__ wh) {
    __shared__ float tt[32][33];
    int t = blockIdx.x;
    const float* src;
    __half* dh;
    int srcN, dstK, n0, k0, nd;

    if (t < 4608) {
        int g = t / 1536, r = t % 1536;
        int l = r >> 8, rr = r & 255;
        n0 = (rr & 15) << 5; k0 = (rr >> 4) << 5;
        const float* w = (g == 0) ? wq : (g == 1) ? wk : wv;
        src = w + (size_t)l * WSZP;
        dh = wh + OFF_QKV + (size_t)l * SZ_QKV;
        srcN = 512; dstK = 512; nd = g * 512 + n0;
    } else if (t < 6144) {
        int r = t - 4608;
        int l = r >> 8, rr = r & 255;
        n0 = (rr & 15) << 5; k0 = (rr >> 4) << 5;
        src = wo + (size_t)l * WSZP;
        dh = wh + OFF_WO + (size_t)l * WSZP;
        srcN = 512; dstK = 512; nd = n0;
    } else if (t < 12288) {
        int r = t - 6144;
        int l = r >> 10, rr = r & 1023;
        n0 = (rr & 63) << 5; k0 = (rr >> 6) << 5;
        src = w1 + (size_t)l * WSZM;
        dh = wh + OFF_W1 + (size_t)l * WSZM;
        srcN = 2048; dstK = 512; nd = n0;
    } else {
        int r = t - 12288;
        int l = r >> 10, rr = r & 1023;
        n0 = (rr & 15) << 5; k0 = (rr >> 4) << 5;
        src = w2 + (size_t)l * WSZM;
        dh = wh + OFF_W2 + (size_t)l * WSZM;
        srcN = 512; dstK = 2048; nd = n0;
    }

    int tx = threadIdx.x, ty = threadIdx.y;
#pragma unroll
    for (int i = 0; i < 4; i++)
        tt[ty + i * 8][tx] = src[(size_t)(k0 + ty + i * 8) * srcN + n0 + tx];
    __syncthreads();
#pragma unroll
    for (int i = 0; i < 4; i++) {
        float v = tt[tx][ty + i * 8];
        dh[(size_t)(nd + ty + i * 8) * dstK + k0 + tx] = __float2half_rn(v);
    }
}

// ============================================================
// LayerNorm (fp32 in; fp16 hi/lo out OR fp32 out)
// ============================================================
template <bool WHF>
__global__ void ln_kernel(const float* __restrict__ x,
                          const float* __restrict__ sc,
                          const float* __restrict__ bi,
                          float* __restrict__ outf,
                          __half* __restrict__ ohi,
                          __half* __restrict__ olo) {
    __shared__ float red[4];
    int t = blockIdx.x;
    const float* xr = x + (size_t)t * Dm;
    float v[4];
    float sum = 0.f;
#pragma unroll
    for (int i = 0; i < 4; i++) { v[i] = xr[threadIdx.x + i * 128]; sum += v[i]; }
#pragma unroll
    for (int o = 16; o; o >>= 1) sum += __shfl_xor_sync(0xffffffffu, sum, o);
    if ((threadIdx.x & 31) == 0) red[threadIdx.x >> 5] = sum;
    __syncthreads();
    float mean = (red[0] + red[1] + red[2] + red[3]) * (1.f / Dm);
    __syncthreads();
    float sq = 0.f;
#pragma unroll
    for (int i = 0; i < 4; i++) { float d = v[i] - mean; sq += d * d; }
#pragma unroll
    for (int o = 16; o; o >>= 1) sq += __shfl_xor_sync(0xffffffffu, sq, o);
    if ((threadIdx.x & 31) == 0) red[threadIdx.x >> 5] = sq;
    __syncthreads();
    float var = (red[0] + red[1] + red[2] + red[3]) * (1.f / Dm);
    float rstd = rsqrtf(var + 1e-6f);
#pragma unroll
    for (int i = 0; i < 4; i++) {
        int idx = threadIdx.x + i * 128;
        float y = (v[i] - mean) * rstd * sc[idx] + bi[idx];
        if (WHF) {
            __half h, L;
            hsplit(y, h, L);
            ohi[(size_t)t * Dm + idx] = h;
            olo[(size_t)t * Dm + idx] = L;
        } else {
            outf[(size_t)t * Dm + idx] = y;
        }
    }
}

// ============================================================
// HMMA fp16 2-term GEMM:
// C[M,N] (+)= (Ahi+Alo)[M,K] @ B[N,K]^T   (B plain fp16)
// CTA 128x128, 8 warps, warp tile 32x64, K-chunk 64,
// 3-stage cp.async (48KB/stage), one sync per chunk.
// ============================================================
#define ST_A_HI 0
#define ST_A_LO 16384
#define ST_B    32768
#define STAGE   49152
#define SMEM_GEMM (3 * STAGE)

template <bool ACCUM, bool RELU, bool BIAS, bool WF32, bool WHF>
__global__ void __launch_bounds__(256, 1)
hgemm(const __half* __restrict__ Ahi, const __half* __restrict__ Alo,
      const __half* __restrict__ B,
      const float* __restrict__ bias, float* __restrict__ C,
      __half* __restrict__ Ohi, __half* __restrict__ Olo,
      int N, int K) {
    extern __shared__ char smem[];
    uint32_t sb = smem_u32(smem);
    int tid = threadIdx.x, wid = tid >> 5, lane = tid & 31;
    int m0 = blockIdx.y * 128, n0 = blockIdx.x * 128;
    int wm = (wid >> 1) * 32, wn = (wid & 1) * 64;

    float acc[2][8][4];
#pragma unroll
    for (int i = 0; i < 2; i++)
#pragma unroll
        for (int j = 0; j < 8; j++)
#pragma unroll
            for (int e = 0; e < 4; e++) acc[i][j][e] = 0.f;

    const int NC = K >> 6;

#define LOAD_CHUNK(c, s) do {                                                   \
    int kt = (c) << 6;                                                          \
    uint32_t st_ = sb + (s) * STAGE;                                            \
    _Pragma("unroll")                                                           \
    for (int i = 0; i < 4; i++) {                                               \
        int u = tid + i * 256;                                                  \
        int row = u >> 3, kc = u & 7;                                           \
        uint32_t so = SWZ((uint32_t)(row * 128 + kc * 16));                     \
        size_t ga = (size_t)(m0 + row) * K + kt + kc * 8;                       \
        size_t gb = (size_t)(n0 + row) * K + kt + kc * 8;                       \
        CP16(st_ + ST_A_HI + so, Ahi + ga);                                     \
        CP16(st_ + ST_A_LO + so, Alo + ga);                                     \
        CP16(st_ + ST_B + so,    B + gb);                                       \
    } } while (0)

    LOAD_CHUNK(0, 0);
    CP_COMMIT();
    LOAD_CHUNK(1, 1);
    CP_COMMIT();

    for (int c = 0; c < NC; c++) {
        if (c + 1 < NC) { CP_WAIT(1); } else { CP_WAIT(0); }
        __syncthreads();
        if (c + 2 < NC) {
            LOAD_CHUNK(c + 2, (c + 2) % 3);
            CP_COMMIT();
        }
        uint32_t st = sb + (c % 3) * STAGE;

#pragma unroll
        for (int ks = 0; ks < 4; ks++) {
            int kb = ks * 32 + ((lane >> 4) & 1) * 16;
            uint32_t ah[2][4], al[2][4];
#pragma unroll
            for (int mf = 0; mf < 2; mf++) {
                uint32_t ro = (uint32_t)((wm + mf * 16 + (lane & 15)) * 128 + kb);
                ldsm4(ah[mf], st + ST_A_HI + SWZ(ro));
                ldsm4(al[mf], st + ST_A_LO + SWZ(ro));
            }
#pragma unroll
            for (int nf = 0; nf < 4; nf++) {
                uint32_t bh[4];
                uint32_t ro = (uint32_t)((wn + nf * 16 + (lane & 15)) * 128 + kb);
                ldsm4(bh, st + ST_B + SWZ(ro));
#pragma unroll
                for (int mf = 0; mf < 2; mf++)
#pragma unroll
                    for (int sl = 0; sl < 2; sl++) {
                        int nb = nf * 2 + sl;
                        mma16816(acc[mf][nb], ah[mf], bh[sl], bh[sl + 2]);
                        mma16816(acc[mf][nb], al[mf], bh[sl], bh[sl + 2]);
                    }
            }
        }
    }

    // epilogue
    int r0 = m0 + wm + (lane >> 2);
    int cb = n0 + wn + (lane & 3) * 2;
#pragma unroll
    for (int mf = 0; mf < 2; mf++)
#pragma unroll
        for (int half2i = 0; half2i < 2; half2i++) {
            int rr = r0 + mf * 16 + half2i * 8;
#pragma unroll
            for (int nb = 0; nb < 8; nb++) {
                int cc = cb + nb * 8;
                float v0 = acc[mf][nb][half2i * 2 + 0];
                float v1 = acc[mf][nb][half2i * 2 + 1];
                if (BIAS) {
                    float2 bv = *(const float2*)(bias + cc);
                    v0 += bv.x; v1 += bv.y;
                }
                if (RELU) { v0 = fmaxf(v0, 0.f); v1 = fmaxf(v1, 0.f); }
                if (ACCUM) {
                    float2 o = *(const float2*)(C + (size_t)rr * N + cc);
                    v0 += o.x; v1 += o.y;
                }
                if (WF32)
                    *(float2*)(C + (size_t)rr * N + cc) = make_float2(v0, v1);
                if (WHF) {
                    __half h0, l0, h1, l1;
                    hsplit(v0, h0, l0);
                    hsplit(v1, h1, l1);
                    *(__half2*)(Ohi + (size_t)rr * N + cc) = __halves2half2(h0, h1);
                    *(__half2*)(Olo + (size_t)rr * N + cc) = __halves2half2(l0, l1);
                }
            }
        }
}

// ============================================================
// Local block attention (reads packed qkv fp32; fp16 hi/lo out)
// ============================================================
__global__ void attn_kernel(const float* __restrict__ qkv,
                            const int* __restrict__ inputs,
                            __half* __restrict__ ahi,
                            __half* __restrict__ alo,
                            int lp) {
    __shared__ float buf0[64 * 64];
    __shared__ float buf1[64 * 64];
    __shared__ float maskS[64];

    int n = blockIdx.x, h = blockIdx.y, b = blockIdx.z;
    int tid = threadIdx.x;
    int base = n * 64 - lp;

#pragma unroll
    for (int i = 0; i < 4; i++) {
        int t4 = tid + i * 256;
        int row = t4 >> 4, c4 = t4 & 15;
        int gt = base + row;
        float4 qv = make_float4(0.f, 0.f, 0.f, 0.f);
        float4 kv = qv;
        if (gt >= 0 && gt < Tt) {
            size_t off = ((size_t)(b * Tt + gt)) * 1536 + h * HDm;
            qv = ((const float4*)(qkv + off))[c4];
            kv = ((const float4*)(qkv + off + 512))[c4];
        }
        ((float4*)(buf0 + row * 64))[c4] = qv;
        ((float4*)(buf1 + row * 64))[c4] = kv;
    }
    if (tid < 64) {
        int gt = base + tid;
        maskS[tid] = (gt >= 0 && gt < Tt && inputs[b * Tt + gt] > 0) ? 1.f : 0.f;
    }
    __syncthreads();

    int qr = tid >> 2;
    int kc0 = (tid & 3) * 16;
    float acc[16];
#pragma unroll
    for (int j = 0; j < 16; j++) acc[j] = 0.f;
#pragma unroll
    for (int f4 = 0; f4 < 16; f4++) {
        float4 qv = ((float4*)(buf0 + qr * 64))[f4];
#pragma unroll
        for (int j = 0; j < 16; j++) {
            float4 kv = ((float4*)(buf1 + (kc0 + j) * 64))[f4];
            acc[j] += qv.x * kv.x + qv.y * kv.y + qv.z * kv.z + qv.w * kv.w;
        }
    }
    __syncthreads();

#pragma unroll
    for (int j = 0; j < 16; j++)
        buf0[qr * 64 + kc0 + j] = (maskS[kc0 + j] > 0.f) ? acc[j] * 0.125f : -1e9f;

#pragma unroll
    for (int i = 0; i < 4; i++) {
        int t4 = tid + i * 256;
        int row = t4 >> 4, c4 = t4 & 15;
        int gt = base + row;
        float4 vv = make_float4(0.f, 0.f, 0.f, 0.f);
        if (gt >= 0 && gt < Tt)
            vv = ((const float4*)(qkv + ((size_t)(b * Tt + gt)) * 1536 + h * HDm + 1024))[c4];
        ((float4*)(buf1 + row * 64))[c4] = vv;
    }
    __syncthreads();

    if (tid < 64) {
        float* row = buf0 + tid * 64;
        float m = -1e30f;
#pragma unroll 8
        for (int i2 = 0; i2 < 64; i2++) m = fmaxf(m, row[i2]);
        float s = 0.f;
#pragma unroll 8
        for (int i2 = 0; i2 < 64; i2++) { float e = expf(row[i2] - m); row[i2] = e; s += e; }
        float inv = 1.f / s;
#pragma unroll 8
        for (int i2 = 0; i2 < 64; i2++) row[i2] *= inv;
    }
    __syncthreads();

    float o[16];
#pragma unroll
    for (int j = 0; j < 16; j++) o[j] = 0.f;
    for (int kk = 0; kk < 64; kk++) {
        float p = buf0[qr * 64 + kk];
#pragma unroll
        for (int j4 = 0; j4 < 4; j4++) {
            float4 vv = ((float4*)(buf1 + kk * 64 + kc0))[j4];
            o[j4 * 4 + 0] += p * vv.x;
            o[j4 * 4 + 1] += p * vv.y;
            o[j4 * 4 + 2] += p * vv.z;
            o[j4 * 4 + 3] += p * vv.w;
        }
    }
    int gt = base + qr;
    if (gt >= 0 && gt < Tt) {
        size_t ob = ((size_t)(b * Tt + gt)) * Dm + h * HDm + kc0;
#pragma unroll
        for (int j = 0; j < 16; j += 2) {
            __half h0, l0, h1, l1;
            hsplit(o[j], h0, l0);
            hsplit(o[j + 1], h1, l1);
            *(__half2*)(ahi + ob + j) = __halves2half2(h0, h1);
            *(__half2*)(alo + ob + j) = __halves2half2(l0, l1);
        }
    }
}

// ============================================================
// Host driver
// ============================================================
extern "C" void kernel_launch(void* const* d_in, const int* in_sizes, int n_in,
                              void* d_out, int out_size) {
    const int*   inputs = (const int*)  d_in[0];
    const float* embed  = (const float*)d_in[1];
    const float* wq     = (const float*)d_in[2];
    const float* wk     = (const float*)d_in[3];
    const float* wv     = (const float*)d_in[4];
    const float* wo     = (const float*)d_in[5];
    const float* ln1_s  = (const float*)d_in[6];
    const float* ln1_b  = (const float*)d_in[7];
    const float* ln2_s  = (const float*)d_in[8];
    const float* ln2_b  = (const float*)d_in[9];
    const float* w1     = (const float*)d_in[10];
    const float* b1     = (const float*)d_in[11];
    const float* w2     = (const float*)d_in[12];
    const float* b2     = (const float*)d_in[13];
    const float* lnf_s  = (const float*)d_in[14];
    const float* lnf_b  = (const float*)d_in[15];

    float *x, *qkv;
    __half *hhi, *hlo, *ahi, *alo, *mhi, *mlo, *wh;
    cudaGetSymbolAddress((void**)&x,   g_x);
    cudaGetSymbolAddress((void**)&qkv, g_qkv);
    cudaGetSymbolAddress((void**)&hhi, g_hhi);
    cudaGetSymbolAddress((void**)&hlo, g_hlo);
    cudaGetSymbolAddress((void**)&ahi, g_ahi);
    cudaGetSymbolAddress((void**)&alo, g_alo);
    cudaGetSymbolAddress((void**)&mhi, g_mhi);
    cudaGetSymbolAddress((void**)&mlo, g_mlo);
    cudaGetSymbolAddress((void**)&wh,  g_wh);

    cudaFuncSetAttribute(hgemm<false,false,false,true,false>, cudaFuncAttributeMaxDynamicSharedMemorySize, SMEM_GEMM);
    cudaFuncSetAttribute(hgemm<true, false,false,true,false>, cudaFuncAttributeMaxDynamicSharedMemorySize, SMEM_GEMM);
    cudaFuncSetAttribute(hgemm<false,true, true, false,true>, cudaFuncAttributeMaxDynamicSharedMemorySize, SMEM_GEMM);
    cudaFuncSetAttribute(hgemm<true, false,true, true, false>, cudaFuncAttributeMaxDynamicSharedMemorySize, SMEM_GEMM);

    wprep_all<<<18432, dim3(32, 8)>>>(wq, wk, wv, wo, w1, w2, wh);
    embed_kernel<<<(TOK * Dm) / 256, 256>>>(inputs, embed, x);

    dim3 gQKV(1536 / 128, TOK / 128);
    dim3 gP(Dm / 128, TOK / 128);
    dim3 gM1(MLPD / 128, TOK / 128);

    for (int l = 0; l < Lnum; l++) {
        int lp = (l & 1) ? 32 : 0;
        int nb = (l & 1) ? (Tt + 64) / 64 : Tt / 64;

        ln_kernel<true><<<TOK, 128>>>(x, ln1_s + l * Dm, ln1_b + l * Dm,
                                      nullptr, hhi, hlo);

        hgemm<false,false,false,true,false><<<gQKV, 256, SMEM_GEMM>>>(
            hhi, hlo, wh + OFF_QKV + (size_t)l * SZ_QKV,
            nullptr, qkv, nullptr, nullptr, 1536, Dm);

        attn_kernel<<<dim3(nb, Hh, Bb), 256>>>(qkv, inputs, ahi, alo, lp);

        hgemm<true,false,false,true,false><<<gP, 256, SMEM_GEMM>>>(
            ahi, alo, wh + OFF_WO + (size_t)l * WSZP,
            nullptr, x, nullptr, nullptr, Dm, Dm);

        ln_kernel<true><<<TOK, 128>>>(x, ln2_s + l * Dm, ln2_b + l * Dm,
                                      nullptr, hhi, hlo);

        hgemm<false,true,true,false,true><<<gM1, 256, SMEM_GEMM>>>(
            hhi, hlo, wh + OFF_W1 + (size_t)l * WSZM,
            b1 + (size_t)l * MLPD, nullptr, mhi, mlo, MLPD, Dm);

        hgemm<true,false,true,true,false><<<gP, 256, SMEM_GEMM>>>(
            mhi, mlo, wh + OFF_W2 + (size_t)l * WSZM,
            b2 + (size_t)l * Dm, x, nullptr, nullptr, Dm, MLPD);
    }

    ln_kernel<false><<<TOK, 128>>>(x, lnf_s, lnf_b, (float*)d_out, nullptr, nullptr);
}

// round 8
// speedup vs baseline: 1.7384x; 1.4333x over previous
#include <cuda_runtime.h>
#include <cuda_fp16.h>
#include <math.h>
#include <stdint.h>

#define TOK   16384
#define Dm    512
#define Tt    4096
#define Bb    4
#define Hh    8
#define HDm   64
#define Lnum  6
#define MLPD  2048

#define WSZP  (Dm*Dm)
#define WSZM  (Dm*MLPD)
#define SZ_QKV (3*WSZP)
#define OFF_QKV 0
#define OFF_WO (6*SZ_QKV)
#define OFF_W1 (OFF_WO + 6*WSZP)
#define OFF_W2 (OFF_W1 + 6*WSZM)
#define WTOT   (OFF_W2 + 6*WSZM)

// ---------------- scratch (device globals) ----------------
__device__ __align__(128) float g_x[TOK * Dm];
__device__ __align__(128) float g_qkv[TOK * 3 * Dm];
__device__ __align__(128) __half g_h[TOK * Dm];
__device__ __align__(128) __half g_a[TOK * Dm];
__device__ __align__(128) __half g_m[(size_t)TOK * MLPD];
__device__ __align__(128) __half g_wh[WTOT];

// ---------------- helpers ----------------
__device__ __forceinline__ uint32_t smem_u32(const void* p) {
    uint32_t a;
    asm("{ .reg .u64 t; cvta.to.shared.u64 t, %1; cvt.u32.u64 %0, t; }" : "=r"(a) : "l"(p));
    return a;
}
#define SWZ(o) ((o) ^ (((o) >> 3) & 0x70))

#define CP16(dst, src) \
    asm volatile("cp.async.cg.shared.global [%0], [%1], 16;" :: "r"(dst), "l"(src) : "memory")
#define CP_COMMIT() asm volatile("cp.async.commit_group;" ::: "memory")
#define CP_WAIT(n)  asm volatile("cp.async.wait_group %0;" :: "n"(n) : "memory")

__device__ __forceinline__ void ldsm4(uint32_t* r, uint32_t a) {
    asm volatile("ldmatrix.sync.aligned.m8n8.x4.shared.b16 {%0,%1,%2,%3}, [%4];"
                 : "=r"(r[0]), "=r"(r[1]), "=r"(r[2]), "=r"(r[3]) : "r"(a));
}
__device__ __forceinline__ void mma16816(float* c, const uint32_t* a,
                                         uint32_t b0, uint32_t b1) {
    asm volatile("mma.sync.aligned.m16n8k16.row.col.f32.f16.f16.f32 "
                 "{%0,%1,%2,%3},{%4,%5,%6,%7},{%8,%9},{%0,%1,%2,%3};"
                 : "+f"(c[0]), "+f"(c[1]), "+f"(c[2]), "+f"(c[3])
                 : "r"(a[0]), "r"(a[1]), "r"(a[2]), "r"(a[3]), "r"(b0), "r"(b1));
}

// ============================================================
// Embedding + PE
// ============================================================
__global__ void embed_kernel(const int* __restrict__ inputs,
                             const float* __restrict__ embed,
                             float* __restrict__ x) {
    size_t id = (size_t)blockIdx.x * blockDim.x + threadIdx.x;
    int token = (int)(id >> 9);
    int d = (int)(id & 511);
    int pos = token & (Tt - 1);
    int tok = inputs[token];
    int i = (d < 256) ? d : d - 256;
    const float c = (float)(-9.210340371976184 / 512.0);
    float div = expf((float)(2 * i) * c);
    float ang = (float)pos * div;
    float pe = (d < 256) ? sinf(ang) : cosf(ang);
    x[id] = embed[(size_t)tok * Dm + d] + pe;
}

// ============================================================
// Fused weight prep (one launch): fp32 [K][N] -> fp16 [N][K]
// ============================================================
__global__ void wprep_all(const float* __restrict__ wq, const float* __restrict__ wk,
                          const float* __restrict__ wv, const float* __restrict__ wo,
                          const float* __restrict__ w1, const float* __restrict__ w2,
                          __half* __restrict__ wh) {
    __shared__ float tt[32][33];
    int t = blockIdx.x;
    const float* src;
    __half* dh;
    int srcN, dstK, n0, k0, nd;

    if (t < 4608) {
        int g = t / 1536, r = t % 1536;
        int l = r >> 8, rr = r & 255;
        n0 = (rr & 15) << 5; k0 = (rr >> 4) << 5;
        const float* w = (g == 0) ? wq : (g == 1) ? wk : wv;
        src = w + (size_t)l * WSZP;
        dh = wh + OFF_QKV + (size_t)l * SZ_QKV;
        srcN = 512; dstK = 512; nd = g * 512 + n0;
    } else if (t < 6144) {
        int r = t - 4608;
        int l = r >> 8, rr = r & 255;
        n0 = (rr & 15) << 5; k0 = (rr >> 4) << 5;
        src = wo + (size_t)l * WSZP;
        dh = wh + OFF_WO + (size_t)l * WSZP;
        srcN = 512; dstK = 512; nd = n0;
    } else if (t < 12288) {
        int r = t - 6144;
        int l = r >> 10, rr = r & 1023;
        n0 = (rr & 63) << 5; k0 = (rr >> 6) << 5;
        src = w1 + (size_t)l * WSZM;
        dh = wh + OFF_W1 + (size_t)l * WSZM;
        srcN = 2048; dstK = 512; nd = n0;
    } else {
        int r = t - 12288;
        int l = r >> 10, rr = r & 1023;
        n0 = (rr & 15) << 5; k0 = (rr >> 4) << 5;
        src = w2 + (size_t)l * WSZM;
        dh = wh + OFF_W2 + (size_t)l * WSZM;
        srcN = 512; dstK = 2048; nd = n0;
    }

    int tx = threadIdx.x, ty = threadIdx.y;
#pragma unroll
    for (int i = 0; i < 4; i++)
        tt[ty + i * 8][tx] = src[(size_t)(k0 + ty + i * 8) * srcN + n0 + tx];
    __syncthreads();
#pragma unroll
    for (int i = 0; i < 4; i++) {
        float v = tt[tx][ty + i * 8];
        dh[(size_t)(nd + ty + i * 8) * dstK + k0 + tx] = __float2half_rn(v);
    }
}

// ============================================================
// LayerNorm (fp32 in; fp16 out OR fp32 out)
// ============================================================
template <bool WHF>
__global__ void ln_kernel(const float* __restrict__ x,
                          const float* __restrict__ sc,
                          const float* __restrict__ bi,
                          float* __restrict__ outf,
                          __half* __restrict__ oh) {
    __shared__ float red[4];
    int t = blockIdx.x;
    const float* xr = x + (size_t)t * Dm;
    float v[4];
    float sum = 0.f;
#pragma unroll
    for (int i = 0; i < 4; i++) { v[i] = xr[threadIdx.x + i * 128]; sum += v[i]; }
#pragma unroll
    for (int o = 16; o; o >>= 1) sum += __shfl_xor_sync(0xffffffffu, sum, o);
    if ((threadIdx.x & 31) == 0) red[threadIdx.x >> 5] = sum;
    __syncthreads();
    float mean = (red[0] + red[1] + red[2] + red[3]) * (1.f / Dm);
    __syncthreads();
    float sq = 0.f;
#pragma unroll
    for (int i = 0; i < 4; i++) { float d = v[i] - mean; sq += d * d; }
#pragma unroll
    for (int o = 16; o; o >>= 1) sq += __shfl_xor_sync(0xffffffffu, sq, o);
    if ((threadIdx.x & 31) == 0) red[threadIdx.x >> 5] = sq;
    __syncthreads();
    float var = (red[0] + red[1] + red[2] + red[3]) * (1.f / Dm);
    float rstd = rsqrtf(var + 1e-6f);
#pragma unroll
    for (int i = 0; i < 4; i++) {
        int idx = threadIdx.x + i * 128;
        float y = (v[i] - mean) * rstd * sc[idx] + bi[idx];
        if (WHF) oh[(size_t)t * Dm + idx] = __float2half_rn(y);
        else     outf[(size_t)t * Dm + idx] = y;
    }
}

// ============================================================
// HMMA fp16 GEMM: C[M,N] (+)= A[M,K] @ B[N,K]^T
// CTA 128x128, 8 warps, warp tile 32x64, K-chunk 64,
// 3-stage cp.async (32KB/stage), one sync per chunk.
// ============================================================
#define ST_B    16384
#define STAGE   32768
#define SMEM_GEMM (3 * STAGE)

template <bool ACCUM, bool RELU, bool BIAS, bool WF32, bool WHF>
__global__ void __launch_bounds__(256, 2)
hgemm(const __half* __restrict__ A, const __half* __restrict__ B,
      const float* __restrict__ bias, float* __restrict__ C,
      __half* __restrict__ O,
      int N, int K) {
    extern __shared__ char smem[];
    uint32_t sb = smem_u32(smem);
    int tid = threadIdx.x, wid = tid >> 5, lane = tid & 31;
    int m0 = blockIdx.y * 128, n0 = blockIdx.x * 128;
    int wm = (wid >> 1) * 32, wn = (wid & 1) * 64;

    float acc[2][8][4];
#pragma unroll
    for (int i = 0; i < 2; i++)
#pragma unroll
        for (int j = 0; j < 8; j++)
#pragma unroll
            for (int e = 0; e < 4; e++) acc[i][j][e] = 0.f;

    const int NC = K >> 6;

#define LOAD_CHUNK(c, s) do {                                                   \
    int kt = (c) << 6;                                                          \
    uint32_t st_ = sb + (s) * STAGE;                                            \
    _Pragma("unroll")                                                           \
    for (int i = 0; i < 4; i++) {                                               \
        int u = tid + i * 256;                                                  \
        int row = u >> 3, kc = u & 7;                                           \
        uint32_t so = SWZ((uint32_t)(row * 128 + kc * 16));                     \
        size_t ga = (size_t)(m0 + row) * K + kt + kc * 8;                       \
        size_t gb = (size_t)(n0 + row) * K + kt + kc * 8;                       \
        CP16(st_ + so,        A + ga);                                          \
        CP16(st_ + ST_B + so, B + gb);                                          \
    } } while (0)

    LOAD_CHUNK(0, 0);
    CP_COMMIT();
    LOAD_CHUNK(1, 1);
    CP_COMMIT();

    for (int c = 0; c < NC; c++) {
        if (c + 1 < NC) { CP_WAIT(1); } else { CP_WAIT(0); }
        __syncthreads();
        if (c + 2 < NC) {
            LOAD_CHUNK(c + 2, (c + 2) % 3);
            CP_COMMIT();
        }
        uint32_t st = sb + (c % 3) * STAGE;

#pragma unroll
        for (int ks = 0; ks < 4; ks++) {
            int kb = ks * 32 + ((lane >> 4) & 1) * 16;
            uint32_t ah[2][4];
#pragma unroll
            for (int mf = 0; mf < 2; mf++) {
                uint32_t ro = (uint32_t)((wm + mf * 16 + (lane & 15)) * 128 + kb);
                ldsm4(ah[mf], st + SWZ(ro));
            }
#pragma unroll
            for (int nf = 0; nf < 4; nf++) {
                uint32_t bh[4];
                uint32_t ro = (uint32_t)((wn + nf * 16 + (lane & 15)) * 128 + kb);
                ldsm4(bh, st + ST_B + SWZ(ro));
#pragma unroll
                for (int mf = 0; mf < 2; mf++)
#pragma unroll
                    for (int sl = 0; sl < 2; sl++)
                        mma16816(acc[mf][nf * 2 + sl], ah[mf], bh[sl], bh[sl + 2]);
            }
        }
    }

    // epilogue
    int r0 = m0 + wm + (lane >> 2);
    int cb = n0 + wn + (lane & 3) * 2;
#pragma unroll
    for (int mf = 0; mf < 2; mf++)
#pragma unroll
        for (int hf = 0; hf < 2; hf++) {
            int rr = r0 + mf * 16 + hf * 8;
#pragma unroll
            for (int nb = 0; nb < 8; nb++) {
                int cc = cb + nb * 8;
                float v0 = acc[mf][nb][hf * 2 + 0];
                float v1 = acc[mf][nb][hf * 2 + 1];
                if (BIAS) {
                    float2 bv = *(const float2*)(bias + cc);
                    v0 += bv.x; v1 += bv.y;
                }
                if (RELU) { v0 = fmaxf(v0, 0.f); v1 = fmaxf(v1, 0.f); }
                if (ACCUM) {
                    float2 o = *(const float2*)(C + (size_t)rr * N + cc);
                    v0 += o.x; v1 += o.y;
                }
                if (WF32)
                    *(float2*)(C + (size_t)rr * N + cc) = make_float2(v0, v1);
                if (WHF)
                    *(__half2*)(O + (size_t)rr * N + cc) =
                        __halves2half2(__float2half_rn(v0), __float2half_rn(v1));
            }
        }
}

// ============================================================
// Local block attention (reads packed qkv fp32; fp16 out)
// ============================================================
__global__ void attn_kernel(const float* __restrict__ qkv,
                            const int* __restrict__ inputs,
                            __half* __restrict__ aout,
                            int lp) {
    __shared__ float buf0[64 * 64];
    __shared__ float buf1[64 * 64];
    __shared__ float maskS[64];

    int n = blockIdx.x, h = blockIdx.y, b = blockIdx.z;
    int tid = threadIdx.x;
    int base = n * 64 - lp;

#pragma unroll
    for (int i = 0; i < 4; i++) {
        int t4 = tid + i * 256;
        int row = t4 >> 4, c4 = t4 & 15;
        int gt = base + row;
        float4 qv = make_float4(0.f, 0.f, 0.f, 0.f);
        float4 kv = qv;
        if (gt >= 0 && gt < Tt) {
            size_t off = ((size_t)(b * Tt + gt)) * 1536 + h * HDm;
            qv = ((const float4*)(qkv + off))[c4];
            kv = ((const float4*)(qkv + off + 512))[c4];
        }
        ((float4*)(buf0 + row * 64))[c4] = qv;
        ((float4*)(buf1 + row * 64))[c4] = kv;
    }
    if (tid < 64) {
        int gt = base + tid;
        maskS[tid] = (gt >= 0 && gt < Tt && inputs[b * Tt + gt] > 0) ? 1.f : 0.f;
    }
    __syncthreads();

    int qr = tid >> 2;
    int kc0 = (tid & 3) * 16;
    float acc[16];
#pragma unroll
    for (int j = 0; j < 16; j++) acc[j] = 0.f;
#pragma unroll
    for (int f4 = 0; f4 < 16; f4++) {
        float4 qv = ((float4*)(buf0 + qr * 64))[f4];
#pragma unroll
        for (int j = 0; j < 16; j++) {
            float4 kv = ((float4*)(buf1 + (kc0 + j) * 64))[f4];
            acc[j] += qv.x * kv.x + qv.y * kv.y + qv.z * kv.z + qv.w * kv.w;
        }
    }
    __syncthreads();

#pragma unroll
    for (int j = 0; j < 16; j++)
        buf0[qr * 64 + kc0 + j] = (maskS[kc0 + j] > 0.f) ? acc[j] * 0.125f : -1e9f;

#pragma unroll
    for (int i = 0; i < 4; i++) {
        int t4 = tid + i * 256;
        int row = t4 >> 4, c4 = t4 & 15;
        int gt = base + row;
        float4 vv = make_float4(0.f, 0.f, 0.f, 0.f);
        if (gt >= 0 && gt < Tt)
            vv = ((const float4*)(qkv + ((size_t)(b * Tt + gt)) * 1536 + h * HDm + 1024))[c4];
        ((float4*)(buf1 + row * 64))[c4] = vv;
    }
    __syncthreads();

    if (tid < 64) {
        float* row = buf0 + tid * 64;
        float m = -1e30f;
#pragma unroll 8
        for (int i2 = 0; i2 < 64; i2++) m = fmaxf(m, row[i2]);
        float s = 0.f;
#pragma unroll 8
        for (int i2 = 0; i2 < 64; i2++) { float e = expf(row[i2] - m); row[i2] = e; s += e; }
        float inv = 1.f / s;
#pragma unroll 8
        for (int i2 = 0; i2 < 64; i2++) row[i2] *= inv;
    }
    __syncthreads();

    float o[16];
#pragma unroll
    for (int j = 0; j < 16; j++) o[j] = 0.f;
    for (int kk = 0; kk < 64; kk++) {
        float p = buf0[qr * 64 + kk];
#pragma unroll
        for (int j4 = 0; j4 < 4; j4++) {
            float4 vv = ((float4*)(buf1 + kk * 64 + kc0))[j4];
            o[j4 * 4 + 0] += p * vv.x;
            o[j4 * 4 + 1] += p * vv.y;
            o[j4 * 4 + 2] += p * vv.z;
            o[j4 * 4 + 3] += p * vv.w;
        }
    }
    int gt = base + qr;
    if (gt >= 0 && gt < Tt) {
        size_t ob = ((size_t)(b * Tt + gt)) * Dm + h * HDm + kc0;
#pragma unroll
        for (int j = 0; j < 16; j += 2)
            *(__half2*)(aout + ob + j) =
                __halves2half2(__float2half_rn(o[j]), __float2half_rn(o[j + 1]));
    }
}

// ============================================================
// Host driver
// ============================================================
extern "C" void kernel_launch(void* const* d_in, const int* in_sizes, int n_in,
                              void* d_out, int out_size) {
    const int*   inputs = (const int*)  d_in[0];
    const float* embed  = (const float*)d_in[1];
    const float* wq     = (const float*)d_in[2];
    const float* wk     = (const float*)d_in[3];
    const float* wv     = (const float*)d_in[4];
    const float* wo     = (const float*)d_in[5];
    const float* ln1_s  = (const float*)d_in[6];
    const float* ln1_b  = (const float*)d_in[7];
    const float* ln2_s  = (const float*)d_in[8];
    const float* ln2_b  = (const float*)d_in[9];
    const float* w1     = (const float*)d_in[10];
    const float* b1     = (const float*)d_in[11];
    const float* w2     = (const float*)d_in[12];
    const float* b2     = (const float*)d_in[13];
    const float* lnf_s  = (const float*)d_in[14];
    const float* lnf_b  = (const float*)d_in[15];

    float *x, *qkv;
    __half *h, *a, *m, *wh;
    cudaGetSymbolAddress((void**)&x,   g_x);
    cudaGetSymbolAddress((void**)&qkv, g_qkv);
    cudaGetSymbolAddress((void**)&h,   g_h);
    cudaGetSymbolAddress((void**)&a,   g_a);
    cudaGetSymbolAddress((void**)&m,   g_m);
    cudaGetSymbolAddress((void**)&wh,  g_wh);

    cudaFuncSetAttribute(hgemm<false,false,false,true,false>, cudaFuncAttributeMaxDynamicSharedMemorySize, SMEM_GEMM);
    cudaFuncSetAttribute(hgemm<true, false,false,true,false>, cudaFuncAttributeMaxDynamicSharedMemorySize, SMEM_GEMM);
    cudaFuncSetAttribute(hgemm<false,true, true, false,true>, cudaFuncAttributeMaxDynamicSharedMemorySize, SMEM_GEMM);
    cudaFuncSetAttribute(hgemm<true, false,true, true, false>, cudaFuncAttributeMaxDynamicSharedMemorySize, SMEM_GEMM);

    wprep_all<<<18432, dim3(32, 8)>>>(wq, wk, wv, wo, w1, w2, wh);
    embed_kernel<<<(TOK * Dm) / 256, 256>>>(inputs, embed, x);

    dim3 gQKV(1536 / 128, TOK / 128);
    dim3 gP(Dm / 128, TOK / 128);
    dim3 gM1(MLPD / 128, TOK / 128);

    for (int l = 0; l < Lnum; l++) {
        int lp = (l & 1) ? 32 : 0;
        int nb = (l & 1) ? (Tt + 64) / 64 : Tt / 64;

        ln_kernel<true><<<TOK, 128>>>(x, ln1_s + l * Dm, ln1_b + l * Dm,
                                      nullptr, h);

        hgemm<false,false,false,true,false><<<gQKV, 256, SMEM_GEMM>>>(
            h, wh + OFF_QKV + (size_t)l * SZ_QKV,
            nullptr, qkv, nullptr, 1536, Dm);

        attn_kernel<<<dim3(nb, Hh, Bb), 256>>>(qkv, inputs, a, lp);

        hgemm<true,false,false,true,false><<<gP, 256, SMEM_GEMM>>>(
            a, wh + OFF_WO + (size_t)l * WSZP,
            nullptr, x, nullptr, Dm, Dm);

        ln_kernel<true><<<TOK, 128>>>(x, ln2_s + l * Dm, ln2_b + l * Dm,
                                      nullptr, h);

        hgemm<false,true,true,false,true><<<gM1, 256, SMEM_GEMM>>>(
            h, wh + OFF_W1 + (size_t)l * WSZM,
            b1 + (size_t)l * MLPD, nullptr, m, MLPD, Dm);

        hgemm<true,false,true,true,false><<<gP, 256, SMEM_GEMM>>>(
            m, wh + OFF_W2 + (size_t)l * WSZM,
            b2 + (size_t)l * Dm, x, nullptr, Dm, MLPD);
    }

    ln_kernel<false><<<TOK, 128>>>(x, lnf_s, lnf_b, (float*)d_out, nullptr);
}

// round 9
// speedup vs baseline: 3.9906x; 2.2955x over previous
#include <cuda_runtime.h>
#include <cuda_fp16.h>
#include <math.h>
#include <stdint.h>

#define TOK   16384
#define Dm    512
#define Tt    4096
#define Bb    4
#define Hh    8
#define HDm   64
#define Lnum  6
#define MLPD  2048

#define WSZP  (Dm*Dm)
#define WSZM  (Dm*MLPD)
#define SZ_QKV (3*WSZP)
#define OFF_QKV 0
#define OFF_WO (6*SZ_QKV)
#define OFF_W1 (OFF_WO + 6*WSZP)
#define OFF_W2 (OFF_W1 + 6*WSZM)
#define WTOT   (OFF_W2 + 6*WSZM)

// ---------------- scratch (device globals) ----------------
__device__ __align__(128) float g_x[TOK * Dm];
__device__ __align__(128) __half g_qkvh[TOK * 3 * Dm];
__device__ __align__(128) __half g_h[TOK * Dm];
__device__ __align__(128) __half g_a[TOK * Dm];
__device__ __align__(128) __half g_m[(size_t)TOK * MLPD];
__device__ __align__(128) __half g_wh[WTOT];

// ---------------- helpers ----------------
__device__ __forceinline__ uint32_t smem_u32(const void* p) {
    uint32_t a;
    asm("{ .reg .u64 t; cvta.to.shared.u64 t, %1; cvt.u32.u64 %0, t; }" : "=r"(a) : "l"(p));
    return a;
}
#define SWZ(o) ((o) ^ (((o) >> 3) & 0x70))

#define CP16(dst, src) \
    asm volatile("cp.async.cg.shared.global [%0], [%1], 16;" :: "r"(dst), "l"(src) : "memory")
#define CP_COMMIT() asm volatile("cp.async.commit_group;" ::: "memory")
#define CP_WAIT(n)  asm volatile("cp.async.wait_group %0;" :: "n"(n) : "memory")

__device__ __forceinline__ void ldsm4(uint32_t* r, uint32_t a) {
    asm volatile("ldmatrix.sync.aligned.m8n8.x4.shared.b16 {%0,%1,%2,%3}, [%4];"
                 : "=r"(r[0]), "=r"(r[1]), "=r"(r[2]), "=r"(r[3]) : "r"(a));
}
__device__ __forceinline__ void mma16816(float* c, const uint32_t* a,
                                         uint32_t b0, uint32_t b1) {
    asm volatile("mma.sync.aligned.m16n8k16.row.col.f32.f16.f16.f32 "
                 "{%0,%1,%2,%3},{%4,%5,%6,%7},{%8,%9},{%0,%1,%2,%3};"
                 : "+f"(c[0]), "+f"(c[1]), "+f"(c[2]), "+f"(c[3])
                 : "r"(a[0]), "r"(a[1]), "r"(a[2]), "r"(a[3]), "r"(b0), "r"(b1));
}
__device__ __forceinline__ uint32_t packh2(float a, float b) {
    __half2 h = __halves2half2(__float2half_rn(a), __float2half_rn(b));
    return *(uint32_t*)&h;
}

// ============================================================
// Embedding + PE
// ============================================================
__global__ void embed_kernel(const int* __restrict__ inputs,
                             const float* __restrict__ embed,
                             float* __restrict__ x) {
    size_t id = (size_t)blockIdx.x * blockDim.x + threadIdx.x;
    int token = (int)(id >> 9);
    int d = (int)(id & 511);
    int pos = token & (Tt - 1);
    int tok = inputs[token];
    int i = (d < 256) ? d : d - 256;
    const float c = (float)(-9.210340371976184 / 512.0);
    float div = expf((float)(2 * i) * c);
    float ang = (float)pos * div;
    float pe = (d < 256) ? sinf(ang) : cosf(ang);
    x[id] = embed[(size_t)tok * Dm + d] + pe;
}

// ============================================================
// Fused weight prep (one launch): fp32 [K][N] -> fp16 [N][K]
// ============================================================
__global__ void wprep_all(const float* __restrict__ wq, const float* __restrict__ wk,
                          const float* __restrict__ wv, const float* __restrict__ wo,
                          const float* __restrict__ w1, const float* __restrict__ w2,
                          __half* __restrict__ wh) {
    __shared__ float tt[32][33];
    int t = blockIdx.x;
    const float* src;
    __half* dh;
    int srcN, dstK, n0, k0, nd;

    if (t < 4608) {
        int g = t / 1536, r = t % 1536;
        int l = r >> 8, rr = r & 255;
        n0 = (rr & 15) << 5; k0 = (rr >> 4) << 5;
        const float* w = (g == 0) ? wq : (g == 1) ? wk : wv;
        src = w + (size_t)l * WSZP;
        dh = wh + OFF_QKV + (size_t)l * SZ_QKV;
        srcN = 512; dstK = 512; nd = g * 512 + n0;
    } else if (t < 6144) {
        int r = t - 4608;
        int l = r >> 8, rr = r & 255;
        n0 = (rr & 15) << 5; k0 = (rr >> 4) << 5;
        src = wo + (size_t)l * WSZP;
        dh = wh + OFF_WO + (size_t)l * WSZP;
        srcN = 512; dstK = 512; nd = n0;
    } else if (t < 12288) {
        int r = t - 6144;
        int l = r >> 10, rr = r & 1023;
        n0 = (rr & 63) << 5; k0 = (rr >> 6) << 5;
        src = w1 + (size_t)l * WSZM;
        dh = wh + OFF_W1 + (size_t)l * WSZM;
        srcN = 2048; dstK = 512; nd = n0;
    } else {
        int r = t - 12288;
        int l = r >> 10, rr = r & 1023;
        n0 = (rr & 15) << 5; k0 = (rr >> 4) << 5;
        src = w2 + (size_t)l * WSZM;
        dh = wh + OFF_W2 + (size_t)l * WSZM;
        srcN = 512; dstK = 2048; nd = n0;
    }

    int tx = threadIdx.x, ty = threadIdx.y;
#pragma unroll
    for (int i = 0; i < 4; i++)
        tt[ty + i * 8][tx] = src[(size_t)(k0 + ty + i * 8) * srcN + n0 + tx];
    __syncthreads();
#pragma unroll
    for (int i = 0; i < 4; i++) {
        float v = tt[tx][ty + i * 8];
        dh[(size_t)(nd + ty + i * 8) * dstK + k0 + tx] = __float2half_rn(v);
    }
}

// ============================================================
// LayerNorm (fp32 in; fp16 out OR fp32 out)
// ============================================================
template <bool WHF>
__global__ void ln_kernel(const float* __restrict__ x,
                          const float* __restrict__ sc,
                          const float* __restrict__ bi,
                          float* __restrict__ outf,
                          __half* __restrict__ oh) {
    __shared__ float red[4];
    int t = blockIdx.x;
    const float* xr = x + (size_t)t * Dm;
    float v[4];
    float sum = 0.f;
#pragma unroll
    for (int i = 0; i < 4; i++) { v[i] = xr[threadIdx.x + i * 128]; sum += v[i]; }
#pragma unroll
    for (int o = 16; o; o >>= 1) sum += __shfl_xor_sync(0xffffffffu, sum, o);
    if ((threadIdx.x & 31) == 0) red[threadIdx.x >> 5] = sum;
    __syncthreads();
    float mean = (red[0] + red[1] + red[2] + red[3]) * (1.f / Dm);
    __syncthreads();
    float sq = 0.f;
#pragma unroll
    for (int i = 0; i < 4; i++) { float d = v[i] - mean; sq += d * d; }
#pragma unroll
    for (int o = 16; o; o >>= 1) sq += __shfl_xor_sync(0xffffffffu, sq, o);
    if ((threadIdx.x & 31) == 0) red[threadIdx.x >> 5] = sq;
    __syncthreads();
    float var = (red[0] + red[1] + red[2] + red[3]) * (1.f / Dm);
    float rstd = rsqrtf(var + 1e-6f);
#pragma unroll
    for (int i = 0; i < 4; i++) {
        int idx = threadIdx.x + i * 128;
        float y = (v[i] - mean) * rstd * sc[idx] + bi[idx];
        if (WHF) oh[(size_t)t * Dm + idx] = __float2half_rn(y);
        else     outf[(size_t)t * Dm + idx] = y;
    }
}

// ============================================================
// HMMA fp16 GEMM: C[M,N] (+)= A[M,K] @ B[N,K]^T
// CTA 128x128, 8 warps, warp tile 32x64, K-chunk 64,
// 3-stage cp.async (32KB/stage), one sync per chunk.
// ============================================================
#define ST_B    16384
#define STAGE   32768
#define SMEM_GEMM (3 * STAGE)

template <bool ACCUM, bool RELU, bool BIAS, bool WF32, bool WHF>
__global__ void __launch_bounds__(256, 2)
hgemm(const __half* __restrict__ A, const __half* __restrict__ B,
      const float* __restrict__ bias, float* __restrict__ C,
      __half* __restrict__ O,
      int N, int K) {
    extern __shared__ char smem[];
    uint32_t sb = smem_u32(smem);
    int tid = threadIdx.x, wid = tid >> 5, lane = tid & 31;
    int m0 = blockIdx.y * 128, n0 = blockIdx.x * 128;
    int wm = (wid >> 1) * 32, wn = (wid & 1) * 64;

    float acc[2][8][4];
#pragma unroll
    for (int i = 0; i < 2; i++)
#pragma unroll
        for (int j = 0; j < 8; j++)
#pragma unroll
            for (int e = 0; e < 4; e++) acc[i][j][e] = 0.f;

    const int NC = K >> 6;

#define LOAD_CHUNK(c, s) do {                                                   \
    int kt = (c) << 6;                                                          \
    uint32_t st_ = sb + (s) * STAGE;                                            \
    _Pragma("unroll")                                                           \
    for (int i = 0; i < 4; i++) {                                               \
        int u = tid + i * 256;                                                  \
        int row = u >> 3, kc = u & 7;                                           \
        uint32_t so = SWZ((uint32_t)(row * 128 + kc * 16));                     \
        size_t ga = (size_t)(m0 + row) * K + kt + kc * 8;                       \
        size_t gb = (size_t)(n0 + row) * K + kt + kc * 8;                       \
        CP16(st_ + so,        A + ga);                                          \
        CP16(st_ + ST_B + so, B + gb);                                          \
    } } while (0)

    LOAD_CHUNK(0, 0);
    CP_COMMIT();
    LOAD_CHUNK(1, 1);
    CP_COMMIT();

    for (int c = 0; c < NC; c++) {
        if (c + 1 < NC) { CP_WAIT(1); } else { CP_WAIT(0); }
        __syncthreads();
        if (c + 2 < NC) {
            LOAD_CHUNK(c + 2, (c + 2) % 3);
            CP_COMMIT();
        }
        uint32_t st = sb + (c % 3) * STAGE;

#pragma unroll
        for (int ks = 0; ks < 4; ks++) {
            int kb = ks * 32 + ((lane >> 4) & 1) * 16;
            uint32_t ah[2][4];
#pragma unroll
            for (int mf = 0; mf < 2; mf++) {
                uint32_t ro = (uint32_t)((wm + mf * 16 + (lane & 15)) * 128 + kb);
                ldsm4(ah[mf], st + SWZ(ro));
            }
#pragma unroll
            for (int nf = 0; nf < 4; nf++) {
                uint32_t bh[4];
                uint32_t ro = (uint32_t)((wn + nf * 16 + (lane & 15)) * 128 + kb);
                ldsm4(bh, st + ST_B + SWZ(ro));
#pragma unroll
                for (int mf = 0; mf < 2; mf++)
#pragma unroll
                    for (int sl = 0; sl < 2; sl++)
                        mma16816(acc[mf][nf * 2 + sl], ah[mf], bh[sl], bh[sl + 2]);
            }
        }
    }

    // epilogue
    int r0 = m0 + wm + (lane >> 2);
    int cb = n0 + wn + (lane & 3) * 2;
#pragma unroll
    for (int mf = 0; mf < 2; mf++)
#pragma unroll
        for (int hf = 0; hf < 2; hf++) {
            int rr = r0 + mf * 16 + hf * 8;
#pragma unroll
            for (int nb = 0; nb < 8; nb++) {
                int cc = cb + nb * 8;
                float v0 = acc[mf][nb][hf * 2 + 0];
                float v1 = acc[mf][nb][hf * 2 + 1];
                if (BIAS) {
                    float2 bv = *(const float2*)(bias + cc);
                    v0 += bv.x; v1 += bv.y;
                }
                if (RELU) { v0 = fmaxf(v0, 0.f); v1 = fmaxf(v1, 0.f); }
                if (ACCUM) {
                    float2 o = *(const float2*)(C + (size_t)rr * N + cc);
                    v0 += o.x; v1 += o.y;
                }
                if (WF32)
                    *(float2*)(C + (size_t)rr * N + cc) = make_float2(v0, v1);
                if (WHF)
                    *(__half2*)(O + (size_t)rr * N + cc) =
                        __halves2half2(__float2half_rn(v0), __float2half_rn(v1));
            }
        }
}

// ============================================================
// Tensor-core local block attention.
// 1 CTA (128 thr, 4 warps) per (block n, head h, batch b).
// Q,K swizzled fp16 smem; V stored TRANSPOSED (Vt[hd][ctx]);
// softmax entirely in registers (quad shfl reductions).
// ============================================================
#define AS_Q  0
#define AS_K  8192
#define AS_VT 16384
#define AS_MK 24576

__global__ void __launch_bounds__(128)
attn_mma(const __half* __restrict__ qkvh,
         const int* __restrict__ inputs,
         __half* __restrict__ aout,
         int lp) {
    __shared__ __align__(16) char smem[24576 + 256];
    uint32_t sb = smem_u32(smem);
    float* maskS = (float*)(smem + AS_MK);

    int n = blockIdx.x, h = blockIdx.y, b = blockIdx.z;
    int tid = threadIdx.x, wid = tid >> 5, lane = tid & 31;
    int base = n * 64 - lp;

    // ---- load Q, K (swizzled) and V transposed ----
#pragma unroll
    for (int i = 0; i < 4; i++) {
        int u = tid + i * 128;          // 512 total: row=u/8, chunk c=u%8
        int row = u >> 3, c = u & 7;
        int gt = base + row;
        uint4 qv = make_uint4(0, 0, 0, 0), kv = qv, vv = qv;
        if (gt >= 0 && gt < Tt) {
            const __half* p = qkvh + ((size_t)(b * Tt + gt)) * 1536 + h * HDm;
            qv = *(const uint4*)(p + c * 8);
            kv = *(const uint4*)(p + 512 + c * 8);
            vv = *(const uint4*)(p + 1024 + c * 8);
        }
        uint32_t so = SWZ((uint32_t)(row * 128 + c * 16));
        *(uint4*)(smem + AS_Q + so) = qv;
        *(uint4*)(smem + AS_K + so) = kv;
        __half vh[8];
        *(uint4*)vh = vv;
#pragma unroll
        for (int j = 0; j < 8; j++) {
            uint32_t off = (uint32_t)((c * 8 + j) * 128 + row * 2);
            *(__half*)(smem + AS_VT + SWZ(off)) = vh[j];
        }
    }
    if (tid < 64) {
        int gt = base + tid;
        maskS[tid] = (gt >= 0 && gt < Tt && inputs[b * Tt + gt] > 0) ? 1.f : 0.f;
    }
    __syncthreads();

    int wm = wid * 16;

    // ---- S = Q @ K^T  (warp: 16 rows x 64 cols) ----
    float s[8][4];
#pragma unroll
    for (int j = 0; j < 8; j++)
#pragma unroll
        for (int e = 0; e < 4; e++) s[j][e] = 0.f;

#pragma unroll
    for (int ks = 0; ks < 4; ks++) {
        int kb = ks * 32 + ((lane >> 4) & 1) * 16;
        uint32_t a[4];
        ldsm4(a, sb + AS_Q + SWZ((uint32_t)((wm + (lane & 15)) * 128 + kb)));
#pragma unroll
        for (int nf = 0; nf < 4; nf++) {
            uint32_t bh[4];
            ldsm4(bh, sb + AS_K + SWZ((uint32_t)((nf * 16 + (lane & 15)) * 128 + kb)));
            mma16816(s[nf * 2 + 0], a, bh[0], bh[2]);
            mma16816(s[nf * 2 + 1], a, bh[1], bh[3]);
        }
    }

    // ---- scale + mask (cols shared by both rows of the lane) ----
#pragma unroll
    for (int j = 0; j < 8; j++) {
        int col = j * 8 + (lane & 3) * 2;
        float m0 = maskS[col], m1 = maskS[col + 1];
        s[j][0] = (m0 > 0.f) ? s[j][0] * 0.125f : -1e9f;
        s[j][2] = (m0 > 0.f) ? s[j][2] * 0.125f : -1e9f;
        s[j][1] = (m1 > 0.f) ? s[j][1] * 0.125f : -1e9f;
        s[j][3] = (m1 > 0.f) ? s[j][3] * 0.125f : -1e9f;
    }

    // ---- softmax over 64 cols; rows r=lane>>2 and r+8 ----
    float mx0 = -1e30f, mx1 = -1e30f;
#pragma unroll
    for (int j = 0; j < 8; j++) {
        mx0 = fmaxf(mx0, fmaxf(s[j][0], s[j][1]));
        mx1 = fmaxf(mx1, fmaxf(s[j][2], s[j][3]));
    }
    mx0 = fmaxf(mx0, __shfl_xor_sync(0xffffffffu, mx0, 1));
    mx0 = fmaxf(mx0, __shfl_xor_sync(0xffffffffu, mx0, 2));
    mx1 = fmaxf(mx1, __shfl_xor_sync(0xffffffffu, mx1, 1));
    mx1 = fmaxf(mx1, __shfl_xor_sync(0xffffffffu, mx1, 2));

    float sm0 = 0.f, sm1 = 0.f;
#pragma unroll
    for (int j = 0; j < 8; j++) {
        s[j][0] = expf(s[j][0] - mx0); sm0 += s[j][0];
        s[j][1] = expf(s[j][1] - mx0); sm0 += s[j][1];
        s[j][2] = expf(s[j][2] - mx1); sm1 += s[j][2];
        s[j][3] = expf(s[j][3] - mx1); sm1 += s[j][3];
    }
    sm0 += __shfl_xor_sync(0xffffffffu, sm0, 1);
    sm0 += __shfl_xor_sync(0xffffffffu, sm0, 2);
    sm1 += __shfl_xor_sync(0xffffffffu, sm1, 1);
    sm1 += __shfl_xor_sync(0xffffffffu, sm1, 2);
    float inv0 = 1.f / sm0, inv1 = 1.f / sm1;

    // ---- O = P @ V  (P packed in-register to canonical A-frags) ----
    float o[8][4];
#pragma unroll
    for (int j = 0; j < 8; j++)
#pragma unroll
        for (int e = 0; e < 4; e++) o[j][e] = 0.f;

#pragma unroll
    for (int kk = 0; kk < 4; kk++) {
        uint32_t a[4];
        a[0] = packh2(s[2 * kk][0] * inv0, s[2 * kk][1] * inv0);
        a[1] = packh2(s[2 * kk][2] * inv1, s[2 * kk][3] * inv1);
        a[2] = packh2(s[2 * kk + 1][0] * inv0, s[2 * kk + 1][1] * inv0);
        a[3] = packh2(s[2 * kk + 1][2] * inv1, s[2 * kk + 1][3] * inv1);
        int kb = kk * 32 + ((lane >> 4) & 1) * 16;
#pragma unroll
        for (int nf = 0; nf < 4; nf++) {
            uint32_t bh[4];
            ldsm4(bh, sb + AS_VT + SWZ((uint32_t)((nf * 16 + (lane & 15)) * 128 + kb)));
            mma16816(o[nf * 2 + 0], a, bh[0], bh[2]);
            mma16816(o[nf * 2 + 1], a, bh[1], bh[3]);
        }
    }

    // ---- store fp16 output ----
    int r0 = base + wm + (lane >> 2);
    int r1 = r0 + 8;
#pragma unroll
    for (int j = 0; j < 8; j++) {
        int col = j * 8 + (lane & 3) * 2;
        if (r0 >= 0 && r0 < Tt)
            *(__half2*)(aout + ((size_t)(b * Tt + r0)) * Dm + h * HDm + col) =
                __halves2half2(__float2half_rn(o[j][0]), __float2half_rn(o[j][1]));
        if (r1 >= 0 && r1 < Tt)
            *(__half2*)(aout + ((size_t)(b * Tt + r1)) * Dm + h * HDm + col) =
                __halves2half2(__float2half_rn(o[j][2]), __float2half_rn(o[j][3]));
    }
}

// ============================================================
// Host driver
// ============================================================
extern "C" void kernel_launch(void* const* d_in, const int* in_sizes, int n_in,
                              void* d_out, int out_size) {
    const int*   inputs = (const int*)  d_in[0];
    const float* embed  = (const float*)d_in[1];
    const float* wq     = (const float*)d_in[2];
    const float* wk     = (const float*)d_in[3];
    const float* wv     = (const float*)d_in[4];
    const float* wo     = (const float*)d_in[5];
    const float* ln1_s  = (const float*)d_in[6];
    const float* ln1_b  = (const float*)d_in[7];
    const float* ln2_s  = (const float*)d_in[8];
    const float* ln2_b  = (const float*)d_in[9];
    const float* w1     = (const float*)d_in[10];
    const float* b1     = (const float*)d_in[11];
    const float* w2     = (const float*)d_in[12];
    const float* b2     = (const float*)d_in[13];
    const float* lnf_s  = (const float*)d_in[14];
    const float* lnf_b  = (const float*)d_in[15];

    float* x;
    __half *qkvh, *h, *a, *m, *wh;
    cudaGetSymbolAddress((void**)&x,    g_x);
    cudaGetSymbolAddress((void**)&qkvh, g_qkvh);
    cudaGetSymbolAddress((void**)&h,    g_h);
    cudaGetSymbolAddress((void**)&a,    g_a);
    cudaGetSymbolAddress((void**)&m,    g_m);
    cudaGetSymbolAddress((void**)&wh,   g_wh);

    cudaFuncSetAttribute(hgemm<false,false,false,false,true>, cudaFuncAttributeMaxDynamicSharedMemorySize, SMEM_GEMM);
    cudaFuncSetAttribute(hgemm<true, false,false,true, false>, cudaFuncAttributeMaxDynamicSharedMemorySize, SMEM_GEMM);
    cudaFuncSetAttribute(hgemm<false,true, true, false,true>, cudaFuncAttributeMaxDynamicSharedMemorySize, SMEM_GEMM);
    cudaFuncSetAttribute(hgemm<true, false,true, true, false>, cudaFuncAttributeMaxDynamicSharedMemorySize, SMEM_GEMM);

    wprep_all<<<18432, dim3(32, 8)>>>(wq, wk, wv, wo, w1, w2, wh);
    embed_kernel<<<(TOK * Dm) / 256, 256>>>(inputs, embed, x);

    dim3 gQKV(1536 / 128, TOK / 128);
    dim3 gP(Dm / 128, TOK / 128);
    dim3 gM1(MLPD / 128, TOK / 128);

    for (int l = 0; l < Lnum; l++) {
        int lp = (l & 1) ? 32 : 0;
        int nb = (l & 1) ? (Tt + 64) / 64 : Tt / 64;

        ln_kernel<true><<<TOK, 128>>>(x, ln1_s + l * Dm, ln1_b + l * Dm,
                                      nullptr, h);

        // qkv (fp16) = h @ [wq|wk|wv]
        hgemm<false,false,false,false,true><<<gQKV, 256, SMEM_GEMM>>>(
            h, wh + OFF_QKV + (size_t)l * SZ_QKV,
            nullptr, nullptr, qkvh, 1536, Dm);

        attn_mma<<<dim3(nb, Hh, Bb), 128>>>(qkvh, inputs, a, lp);

        // x += attn @ wo
        hgemm<true,false,false,true,false><<<gP, 256, SMEM_GEMM>>>(
            a, wh + OFF_WO + (size_t)l * WSZP,
            nullptr, x, nullptr, Dm, Dm);

        ln_kernel<true><<<TOK, 128>>>(x, ln2_s + l * Dm, ln2_b + l * Dm,
                                      nullptr, h);

        // m = relu(h @ w1 + b1)  (fp16)
        hgemm<false,true,true,false,true><<<gM1, 256, SMEM_GEMM>>>(
            h, wh + OFF_W1 + (size_t)l * WSZM,
            b1 + (size_t)l * MLPD, nullptr, m, MLPD, Dm);

        // x += m @ w2 + b2
        hgemm<true,false,true,true,false><<<gP, 256, SMEM_GEMM>>>(
            m, wh + OFF_W2 + (size_t)l * WSZM,
            b2 + (size_t)l * Dm, x, nullptr, Dm, MLPD);
    }

    ln_kernel<false><<<TOK, 128>>>(x, lnf_s, lnf_b, (float*)d_out, nullptr);
}

// round 10
// speedup vs baseline: 4.0303x; 1.0100x over previous
#include <cuda_runtime.h>
#include <cuda_fp16.h>
#include <math.h>
#include <stdint.h>

#define TOK   16384
#define Dm    512
#define Tt    4096
#define Bb    4
#define Hh    8
#define HDm   64
#define Lnum  6
#define MLPD  2048

#define WSZP  (Dm*Dm)
#define WSZM  (Dm*MLPD)
#define SZ_QKV (3*WSZP)
#define OFF_QKV 0
#define OFF_WO (6*SZ_QKV)
#define OFF_W1 (OFF_WO + 6*WSZP)
#define OFF_W2 (OFF_W1 + 6*WSZM)
#define WTOT   (OFF_W2 + 6*WSZM)

// ---------------- scratch (device globals) ----------------
__device__ __align__(128) float g_x[TOK * Dm];
__device__ __align__(128) float g_pe[Tt * Dm];
__device__ __align__(128) __half g_qkvh[TOK * 3 * Dm];
__device__ __align__(128) __half g_h[TOK * Dm];
__device__ __align__(128) __half g_a[TOK * Dm];
__device__ __align__(128) __half g_m[(size_t)TOK * MLPD];
__device__ __align__(128) __half g_wh[WTOT];

// ---------------- helpers ----------------
__device__ __forceinline__ uint32_t smem_u32(const void* p) {
    uint32_t a;
    asm("{ .reg .u64 t; cvta.to.shared.u64 t, %1; cvt.u32.u64 %0, t; }" : "=r"(a) : "l"(p));
    return a;
}
#define SWZ(o) ((o) ^ (((o) >> 3) & 0x70))

#define CP16(dst, src) \
    asm volatile("cp.async.cg.shared.global [%0], [%1], 16;" :: "r"(dst), "l"(src) : "memory")
#define CP_COMMIT() asm volatile("cp.async.commit_group;" ::: "memory")
#define CP_WAIT(n)  asm volatile("cp.async.wait_group %0;" :: "n"(n) : "memory")

__device__ __forceinline__ void ldsm4(uint32_t* r, uint32_t a) {
    asm volatile("ldmatrix.sync.aligned.m8n8.x4.shared.b16 {%0,%1,%2,%3}, [%4];"
                 : "=r"(r[0]), "=r"(r[1]), "=r"(r[2]), "=r"(r[3]) : "r"(a));
}
__device__ __forceinline__ void mma16816(float* c, const uint32_t* a,
                                         uint32_t b0, uint32_t b1) {
    asm volatile("mma.sync.aligned.m16n8k16.row.col.f32.f16.f16.f32 "
                 "{%0,%1,%2,%3},{%4,%5,%6,%7},{%8,%9},{%0,%1,%2,%3};"
                 : "+f"(c[0]), "+f"(c[1]), "+f"(c[2]), "+f"(c[3])
                 : "r"(a[0]), "r"(a[1]), "r"(a[2]), "r"(a[3]), "r"(b0), "r"(b1));
}
__device__ __forceinline__ uint32_t packh2(float a, float b) {
    __half2 h = __halves2half2(__float2half_rn(a), __float2half_rn(b));
    return *(uint32_t*)&h;
}

// ============================================================
// PE table: pe[pos][i] = sin(pos*div_i), pe[pos][i+256] = cos
// One sincosf per (pos, i) — shares range reduction.
// ============================================================
__global__ void pe_kernel(float* __restrict__ pe) {
    int id = blockIdx.x * blockDim.x + threadIdx.x;   // over 4096*256
    int pos = id >> 8, i = id & 255;
    const float c = (float)(-9.210340371976184 / 512.0);
    float div = expf((float)(2 * i) * c);
    float ang = (float)pos * div;
    float s, co;
    sincosf(ang, &s, &co);
    pe[pos * Dm + i] = s;
    pe[pos * Dm + i + 256] = co;
}

// ============================================================
// Embedding + PE add (pure bandwidth, float4)
// ============================================================
__global__ void embed_kernel(const int* __restrict__ inputs,
                             const float* __restrict__ embed,
                             const float* __restrict__ pe,
                             float* __restrict__ x) {
    size_t q = (size_t)blockIdx.x * blockDim.x + threadIdx.x;   // over TOK*Dm/4
    int token = (int)(q >> 7);           // /128 float4s per row
    int c4 = (int)(q & 127);
    int pos = token & (Tt - 1);
    int tok = inputs[token];
    float4 e = ((const float4*)(embed + (size_t)tok * Dm))[c4];
    float4 p = ((const float4*)(pe + (size_t)pos * Dm))[c4];
    ((float4*)(x + (size_t)token * Dm))[c4] =
        make_float4(e.x + p.x, e.y + p.y, e.z + p.z, e.w + p.w);
}

// ============================================================
// Fused weight prep (one launch): fp32 [K][N] -> fp16 [N][K]
// ============================================================
__global__ void wprep_all(const float* __restrict__ wq, const float* __restrict__ wk,
                          const float* __restrict__ wv, const float* __restrict__ wo,
                          const float* __restrict__ w1, const float* __restrict__ w2,
                          __half* __restrict__ wh) {
    __shared__ float tt[32][33];
    int t = blockIdx.x;
    const float* src;
    __half* dh;
    int srcN, dstK, n0, k0, nd;

    if (t < 4608) {
        int g = t / 1536, r = t % 1536;
        int l = r >> 8, rr = r & 255;
        n0 = (rr & 15) << 5; k0 = (rr >> 4) << 5;
        const float* w = (g == 0) ? wq : (g == 1) ? wk : wv;
        src = w + (size_t)l * WSZP;
        dh = wh + OFF_QKV + (size_t)l * SZ_QKV;
        srcN = 512; dstK = 512; nd = g * 512 + n0;
    } else if (t < 6144) {
        int r = t - 4608;
        int l = r >> 8, rr = r & 255;
        n0 = (rr & 15) << 5; k0 = (rr >> 4) << 5;
        src = wo + (size_t)l * WSZP;
        dh = wh + OFF_WO + (size_t)l * WSZP;
        srcN = 512; dstK = 512; nd = n0;
    } else if (t < 12288) {
        int r = t - 6144;
        int l = r >> 10, rr = r & 1023;
        n0 = (rr & 63) << 5; k0 = (rr >> 6) << 5;
        src = w1 + (size_t)l * WSZM;
        dh = wh + OFF_W1 + (size_t)l * WSZM;
        srcN = 2048; dstK = 512; nd = n0;
    } else {
        int r = t - 12288;
        int l = r >> 10, rr = r & 1023;
        n0 = (rr & 15) << 5; k0 = (rr >> 4) << 5;
        src = w2 + (size_t)l * WSZM;
        dh = wh + OFF_W2 + (size_t)l * WSZM;
        srcN = 512; dstK = 2048; nd = n0;
    }

    int tx = threadIdx.x, ty = threadIdx.y;
#pragma unroll
    for (int i = 0; i < 4; i++)
        tt[ty + i * 8][tx] = src[(size_t)(k0 + ty + i * 8) * srcN + n0 + tx];
    __syncthreads();
#pragma unroll
    for (int i = 0; i < 4; i++) {
        float v = tt[tx][ty + i * 8];
        dh[(size_t)(nd + ty + i * 8) * dstK + k0 + tx] = __float2half_rn(v);
    }
}

// ============================================================
// LayerNorm — float4 vectorized; 128 threads per token
// ============================================================
template <bool WHF>
__global__ void ln_kernel(const float* __restrict__ x,
                          const float* __restrict__ sc,
                          const float* __restrict__ bi,
                          float* __restrict__ outf,
                          __half* __restrict__ oh) {
    __shared__ float red[4];
    int t = blockIdx.x;
    int tid = threadIdx.x;
    float4 v = ((const float4*)(x + (size_t)t * Dm))[tid];

    float sum = v.x + v.y + v.z + v.w;
#pragma unroll
    for (int o = 16; o; o >>= 1) sum += __shfl_xor_sync(0xffffffffu, sum, o);
    if ((tid & 31) == 0) red[tid >> 5] = sum;
    __syncthreads();
    float mean = (red[0] + red[1] + red[2] + red[3]) * (1.f / Dm);
    __syncthreads();

    float dx = v.x - mean, dy = v.y - mean, dz = v.z - mean, dw = v.w - mean;
    float sq = dx * dx + dy * dy + dz * dz + dw * dw;
#pragma unroll
    for (int o = 16; o; o >>= 1) sq += __shfl_xor_sync(0xffffffffu, sq, o);
    if ((tid & 31) == 0) red[tid >> 5] = sq;
    __syncthreads();
    float var = (red[0] + red[1] + red[2] + red[3]) * (1.f / Dm);
    float rstd = rsqrtf(var + 1e-6f);

    float4 s4 = ((const float4*)sc)[tid];
    float4 b4 = ((const float4*)bi)[tid];
    float y0 = dx * rstd * s4.x + b4.x;
    float y1 = dy * rstd * s4.y + b4.y;
    float y2 = dz * rstd * s4.z + b4.z;
    float y3 = dw * rstd * s4.w + b4.w;

    if (WHF) {
        uint2 o2;
        o2.x = packh2(y0, y1);
        o2.y = packh2(y2, y3);
        ((uint2*)(oh + (size_t)t * Dm))[tid] = o2;
    } else {
        ((float4*)(outf + (size_t)t * Dm))[tid] = make_float4(y0, y1, y2, y3);
    }
}

// ============================================================
// HMMA fp16 GEMM: C[M,N] (+)= A[M,K] @ B[N,K]^T
// CTA 128x128, 8 warps, warp tile 32x64, K-chunk 64,
// 3-stage cp.async (32KB/stage), one sync per chunk.
// ACCUM path uses red.global.add (no C read; 1 add/elem).
// ============================================================
#define ST_B    16384
#define STAGE   32768
#define SMEM_GEMM (3 * STAGE)

template <bool ACCUM, bool RELU, bool BIAS, bool WF32, bool WHF>
__global__ void __launch_bounds__(256, 2)
hgemm(const __half* __restrict__ A, const __half* __restrict__ B,
      const float* __restrict__ bias, float* __restrict__ C,
      __half* __restrict__ O,
      int N, int K) {
    extern __shared__ char smem[];
    uint32_t sb = smem_u32(smem);
    int tid = threadIdx.x, wid = tid >> 5, lane = tid & 31;
    int m0 = blockIdx.y * 128, n0 = blockIdx.x * 128;
    int wm = (wid >> 1) * 32, wn = (wid & 1) * 64;

    float acc[2][8][4];
#pragma unroll
    for (int i = 0; i < 2; i++)
#pragma unroll
        for (int j = 0; j < 8; j++)
#pragma unroll
            for (int e = 0; e < 4; e++) acc[i][j][e] = 0.f;

    const int NC = K >> 6;

#define LOAD_CHUNK(c, s) do {                                                   \
    int kt = (c) << 6;                                                          \
    uint32_t st_ = sb + (s) * STAGE;                                            \
    _Pragma("unroll")                                                           \
    for (int i = 0; i < 4; i++) {                                               \
        int u = tid + i * 256;                                                  \
        int row = u >> 3, kc = u & 7;                                           \
        uint32_t so = SWZ((uint32_t)(row * 128 + kc * 16));                     \
        size_t ga = (size_t)(m0 + row) * K + kt + kc * 8;                       \
        size_t gb = (size_t)(n0 + row) * K + kt + kc * 8;                       \
        CP16(st_ + so,        A + ga);                                          \
        CP16(st_ + ST_B + so, B + gb);                                          \
    } } while (0)

    LOAD_CHUNK(0, 0);
    CP_COMMIT();
    LOAD_CHUNK(1, 1);
    CP_COMMIT();

    for (int c = 0; c < NC; c++) {
        if (c + 1 < NC) { CP_WAIT(1); } else { CP_WAIT(0); }
        __syncthreads();
        if (c + 2 < NC) {
            LOAD_CHUNK(c + 2, (c + 2) % 3);
            CP_COMMIT();
        }
        uint32_t st = sb + (c % 3) * STAGE;

#pragma unroll
        for (int ks = 0; ks < 4; ks++) {
            int kb = ks * 32 + ((lane >> 4) & 1) * 16;
            uint32_t ah[2][4];
#pragma unroll
            for (int mf = 0; mf < 2; mf++) {
                uint32_t ro = (uint32_t)((wm + mf * 16 + (lane & 15)) * 128 + kb);
                ldsm4(ah[mf], st + SWZ(ro));
            }
#pragma unroll
            for (int nf = 0; nf < 4; nf++) {
                uint32_t bh[4];
                uint32_t ro = (uint32_t)((wn + nf * 16 + (lane & 15)) * 128 + kb);
                ldsm4(bh, st + ST_B + SWZ(ro));
#pragma unroll
                for (int mf = 0; mf < 2; mf++)
#pragma unroll
                    for (int sl = 0; sl < 2; sl++)
                        mma16816(acc[mf][nf * 2 + sl], ah[mf], bh[sl], bh[sl + 2]);
            }
        }
    }

    // epilogue
    int r0 = m0 + wm + (lane >> 2);
    int cb = n0 + wn + (lane & 3) * 2;
#pragma unroll
    for (int mf = 0; mf < 2; mf++)
#pragma unroll
        for (int hf = 0; hf < 2; hf++) {
            int rr = r0 + mf * 16 + hf * 8;
#pragma unroll
            for (int nb = 0; nb < 8; nb++) {
                int cc = cb + nb * 8;
                float v0 = acc[mf][nb][hf * 2 + 0];
                float v1 = acc[mf][nb][hf * 2 + 1];
                if (BIAS) {
                    float2 bv = *(const float2*)(bias + cc);
                    v0 += bv.x; v1 += bv.y;
                }
                if (RELU) { v0 = fmaxf(v0, 0.f); v1 = fmaxf(v1, 0.f); }
                if (ACCUM) {
                    atomicAdd(C + (size_t)rr * N + cc, v0);
                    atomicAdd(C + (size_t)rr * N + cc + 1, v1);
                } else if (WF32) {
                    *(float2*)(C + (size_t)rr * N + cc) = make_float2(v0, v1);
                }
                if (WHF)
                    *(__half2*)(O + (size_t)rr * N + cc) =
                        __halves2half2(__float2half_rn(v0), __float2half_rn(v1));
            }
        }
}

// ============================================================
// Tensor-core local block attention.
// 1 CTA (128 thr, 4 warps) per (block n, head h, batch b).
// ============================================================
#define AS_Q  0
#define AS_K  8192
#define AS_VT 16384
#define AS_MK 24576

__global__ void __launch_bounds__(128)
attn_mma(const __half* __restrict__ qkvh,
         const int* __restrict__ inputs,
         __half* __restrict__ aout,
         int lp) {
    __shared__ __align__(16) char smem[24576 + 256];
    uint32_t sb = smem_u32(smem);
    float* maskS = (float*)(smem + AS_MK);

    int n = blockIdx.x, h = blockIdx.y, b = blockIdx.z;
    int tid = threadIdx.x, wid = tid >> 5, lane = tid & 31;
    int base = n * 64 - lp;

#pragma unroll
    for (int i = 0; i < 4; i++) {
        int u = tid + i * 128;
        int row = u >> 3, c = u & 7;
        int gt = base + row;
        uint4 qv = make_uint4(0, 0, 0, 0), kv = qv, vv = qv;
        if (gt >= 0 && gt < Tt) {
            const __half* p = qkvh + ((size_t)(b * Tt + gt)) * 1536 + h * HDm;
            qv = *(const uint4*)(p + c * 8);
            kv = *(const uint4*)(p + 512 + c * 8);
            vv = *(const uint4*)(p + 1024 + c * 8);
        }
        uint32_t so = SWZ((uint32_t)(row * 128 + c * 16));
        *(uint4*)(smem + AS_Q + so) = qv;
        *(uint4*)(smem + AS_K + so) = kv;
        __half vh[8];
        *(uint4*)vh = vv;
#pragma unroll
        for (int j = 0; j < 8; j++) {
            uint32_t off = (uint32_t)((c * 8 + j) * 128 + row * 2);
            *(__half*)(smem + AS_VT + SWZ(off)) = vh[j];
        }
    }
    if (tid < 64) {
        int gt = base + tid;
        maskS[tid] = (gt >= 0 && gt < Tt && inputs[b * Tt + gt] > 0) ? 1.f : 0.f;
    }
    __syncthreads();

    int wm = wid * 16;

    float s[8][4];
#pragma unroll
    for (int j = 0; j < 8; j++)
#pragma unroll
        for (int e = 0; e < 4; e++) s[j][e] = 0.f;

#pragma unroll
    for (int ks = 0; ks < 4; ks++) {
        int kb = ks * 32 + ((lane >> 4) & 1) * 16;
        uint32_t a[4];
        ldsm4(a, sb + AS_Q + SWZ((uint32_t)((wm + (lane & 15)) * 128 + kb)));
#pragma unroll
        for (int nf = 0; nf < 4; nf++) {
            uint32_t bh[4];
            ldsm4(bh, sb + AS_K + SWZ((uint32_t)((nf * 16 + (lane & 15)) * 128 + kb)));
            mma16816(s[nf * 2 + 0], a, bh[0], bh[2]);
            mma16816(s[nf * 2 + 1], a, bh[1], bh[3]);
        }
    }

#pragma unroll
    for (int j = 0; j < 8; j++) {
        int col = j * 8 + (lane & 3) * 2;
        float m0 = maskS[col], m1 = maskS[col + 1];
        s[j][0] = (m0 > 0.f) ? s[j][0] * 0.125f : -1e9f;
        s[j][2] = (m0 > 0.f) ? s[j][2] * 0.125f : -1e9f;
        s[j][1] = (m1 > 0.f) ? s[j][1] * 0.125f : -1e9f;
        s[j][3] = (m1 > 0.f) ? s[j][3] * 0.125f : -1e9f;
    }

    float mx0 = -1e30f, mx1 = -1e30f;
#pragma unroll
    for (int j = 0; j < 8; j++) {
        mx0 = fmaxf(mx0, fmaxf(s[j][0], s[j][1]));
        mx1 = fmaxf(mx1, fmaxf(s[j][2], s[j][3]));
    }
    mx0 = fmaxf(mx0, __shfl_xor_sync(0xffffffffu, mx0, 1));
    mx0 = fmaxf(mx0, __shfl_xor_sync(0xffffffffu, mx0, 2));
    mx1 = fmaxf(mx1, __shfl_xor_sync(0xffffffffu, mx1, 1));
    mx1 = fmaxf(mx1, __shfl_xor_sync(0xffffffffu, mx1, 2));

    float sm0 = 0.f, sm1 = 0.f;
#pragma unroll
    for (int j = 0; j < 8; j++) {
        s[j][0] = expf(s[j][0] - mx0); sm0 += s[j][0];
        s[j][1] = expf(s[j][1] - mx0); sm0 += s[j][1];
        s[j][2] = expf(s[j][2] - mx1); sm1 += s[j][2];
        s[j][3] = expf(s[j][3] - mx1); sm1 += s[j][3];
    }
    sm0 += __shfl_xor_sync(0xffffffffu, sm0, 1);
    sm0 += __shfl_xor_sync(0xffffffffu, sm0, 2);
    sm1 += __shfl_xor_sync(0xffffffffu, sm1, 1);
    sm1 += __shfl_xor_sync(0xffffffffu, sm1, 2);
    float inv0 = 1.f / sm0, inv1 = 1.f / sm1;

    float o[8][4];
#pragma unroll
    for (int j = 0; j < 8; j++)
#pragma unroll
        for (int e = 0; e < 4; e++) o[j][e] = 0.f;

#pragma unroll
    for (int kk = 0; kk < 4; kk++) {
        uint32_t a[4];
        a[0] = packh2(s[2 * kk][0] * inv0, s[2 * kk][1] * inv0);
        a[1] = packh2(s[2 * kk][2] * inv1, s[2 * kk][3] * inv1);
        a[2] = packh2(s[2 * kk + 1][0] * inv0, s[2 * kk + 1][1] * inv0);
        a[3] = packh2(s[2 * kk + 1][2] * inv1, s[2 * kk + 1][3] * inv1);
        int kb = kk * 32 + ((lane >> 4) & 1) * 16;
#pragma unroll
        for (int nf = 0; nf < 4; nf++) {
            uint32_t bh[4];
            ldsm4(bh, sb + AS_VT + SWZ((uint32_t)((nf * 16 + (lane & 15)) * 128 + kb)));
            mma16816(o[nf * 2 + 0], a, bh[0], bh[2]);
            mma16816(o[nf * 2 + 1], a, bh[1], bh[3]);
        }
    }

    int r0 = base + wm + (lane >> 2);
    int r1 = r0 + 8;
#pragma unroll
    for (int j = 0; j < 8; j++) {
        int col = j * 8 + (lane & 3) * 2;
        if (r0 >= 0 && r0 < Tt)
            *(__half2*)(aout + ((size_t)(b * Tt + r0)) * Dm + h * HDm + col) =
                __halves2half2(__float2half_rn(o[j][0]), __float2half_rn(o[j][1]));
        if (r1 >= 0 && r1 < Tt)
            *(__half2*)(aout + ((size_t)(b * Tt + r1)) * Dm + h * HDm + col) =
                __halves2half2(__float2half_rn(o[j][2]), __float2half_rn(o[j][3]));
    }
}

// ============================================================
// Host driver
// ============================================================
extern "C" void kernel_launch(void* const* d_in, const int* in_sizes, int n_in,
                              void* d_out, int out_size) {
    const int*   inputs = (const int*)  d_in[0];
    const float* embed  = (const float*)d_in[1];
    const float* wq     = (const float*)d_in[2];
    const float* wk     = (const float*)d_in[3];
    const float* wv     = (const float*)d_in[4];
    const float* wo     = (const float*)d_in[5];
    const float* ln1_s  = (const float*)d_in[6];
    const float* ln1_b  = (const float*)d_in[7];
    const float* ln2_s  = (const float*)d_in[8];
    const float* ln2_b  = (const float*)d_in[9];
    const float* w1     = (const float*)d_in[10];
    const float* b1     = (const float*)d_in[11];
    const float* w2     = (const float*)d_in[12];
    const float* b2     = (const float*)d_in[13];
    const float* lnf_s  = (const float*)d_in[14];
    const float* lnf_b  = (const float*)d_in[15];

    float *x, *pe;
    __half *qkvh, *h, *a, *m, *wh;
    cudaGetSymbolAddress((void**)&x,    g_x);
    cudaGetSymbolAddress((void**)&pe,   g_pe);
    cudaGetSymbolAddress((void**)&qkvh, g_qkvh);
    cudaGetSymbolAddress((void**)&h,    g_h);
    cudaGetSymbolAddress((void**)&a,    g_a);
    cudaGetSymbolAddress((void**)&m,    g_m);
    cudaGetSymbolAddress((void**)&wh,   g_wh);

    cudaFuncSetAttribute(hgemm<false,false,false,false,true>, cudaFuncAttributeMaxDynamicSharedMemorySize, SMEM_GEMM);
    cudaFuncSetAttribute(hgemm<true, false,false,true, false>, cudaFuncAttributeMaxDynamicSharedMemorySize, SMEM_GEMM);
    cudaFuncSetAttribute(hgemm<false,true, true, false,true>, cudaFuncAttributeMaxDynamicSharedMemorySize, SMEM_GEMM);
    cudaFuncSetAttribute(hgemm<true, false,true, true, false>, cudaFuncAttributeMaxDynamicSharedMemorySize, SMEM_GEMM);

    wprep_all<<<18432, dim3(32, 8)>>>(wq, wk, wv, wo, w1, w2, wh);
    pe_kernel<<<(Tt * 256) / 256, 256>>>(pe);
    embed_kernel<<<(TOK * Dm / 4) / 256, 256>>>(inputs, embed, pe, x);

    dim3 gQKV(1536 / 128, TOK / 128);
    dim3 gP(Dm / 128, TOK / 128);
    dim3 gM1(MLPD / 128, TOK / 128);

    for (int l = 0; l < Lnum; l++) {
        int lp = (l & 1) ? 32 : 0;
        int nb = (l & 1) ? (Tt + 64) / 64 : Tt / 64;

        ln_kernel<true><<<TOK, 128>>>(x, ln1_s + l * Dm, ln1_b + l * Dm,
                                      nullptr, h);

        // qkv (fp16) = h @ [wq|wk|wv]
        hgemm<false,false,false,false,true><<<gQKV, 256, SMEM_GEMM>>>(
            h, wh + OFF_QKV + (size_t)l * SZ_QKV,
            nullptr, nullptr, qkvh, 1536, Dm);

        attn_mma<<<dim3(nb, Hh, Bb), 128>>>(qkvh, inputs, a, lp);

        // x += attn @ wo   (red.global epilogue)
        hgemm<true,false,false,true,false><<<gP, 256, SMEM_GEMM>>>(
            a, wh + OFF_WO + (size_t)l * WSZP,
            nullptr, x, nullptr, Dm, Dm);

        ln_kernel<true><<<TOK, 128>>>(x, ln2_s + l * Dm, ln2_b + l * Dm,
                                      nullptr, h);

        // m = relu(h @ w1 + b1)  (fp16)
        hgemm<false,true,true,false,true><<<gM1, 256, SMEM_GEMM>>>(
            h, wh + OFF_W1 + (size_t)l * WSZM,
            b1 + (size_t)l * MLPD, nullptr, m, MLPD, Dm);

        // x += m @ w2 + b2   (red.global epilogue)
        hgemm<true,false,true,true,false><<<gP, 256, SMEM_GEMM>>>(
            m, wh + OFF_W2 + (size_t)l * WSZM,
            b2 + (size_t)l * Dm, x, nullptr, Dm, MLPD);
    }

    ln_kernel<false><<<TOK, 128>>>(x, lnf_s, lnf_b, (float*)d_out, nullptr);
}

// round 11
// speedup vs baseline: 4.0745x; 1.0110x over previous
#include <cuda_runtime.h>
#include <cuda_fp16.h>
#include <math.h>
#include <stdint.h>

#define TOK   16384
#define Dm    512
#define Tt    4096
#define Bb    4
#define Hh    8
#define HDm   64
#define Lnum  6
#define MLPD  2048

#define WSZP  (Dm*Dm)
#define WSZM  (Dm*MLPD)
#define SZ_QKV (3*WSZP)
#define OFF_QKV 0
#define OFF_WO (6*SZ_QKV)
#define OFF_W1 (OFF_WO + 6*WSZP)
#define OFF_W2 (OFF_W1 + 6*WSZM)
#define WTOT   (OFF_W2 + 6*WSZM)

// ---------------- scratch (device globals) ----------------
__device__ __align__(128) float g_x[TOK * Dm];
__device__ __align__(128) float g_pe[Tt * Dm];
__device__ __align__(128) __half g_qkvh[TOK * 3 * Dm];
__device__ __align__(128) __half g_h[TOK * Dm];
__device__ __align__(128) __half g_a[TOK * Dm];
__device__ __align__(128) __half g_m[(size_t)TOK * MLPD];
__device__ __align__(128) __half g_wh[WTOT];

// ---------------- helpers ----------------
__device__ __forceinline__ uint32_t smem_u32(const void* p) {
    uint32_t a;
    asm("{ .reg .u64 t; cvta.to.shared.u64 t, %1; cvt.u32.u64 %0, t; }" : "=r"(a) : "l"(p));
    return a;
}
#define SWZ(o) ((o) ^ (((o) >> 3) & 0x70))

#define CP16(dst, src) \
    asm volatile("cp.async.cg.shared.global [%0], [%1], 16;" :: "r"(dst), "l"(src) : "memory")
#define CP_COMMIT() asm volatile("cp.async.commit_group;" ::: "memory")
#define CP_WAIT(n)  asm volatile("cp.async.wait_group %0;" :: "n"(n) : "memory")

__device__ __forceinline__ void ldsm4(uint32_t* r, uint32_t a) {
    asm volatile("ldmatrix.sync.aligned.m8n8.x4.shared.b16 {%0,%1,%2,%3}, [%4];"
                 : "=r"(r[0]), "=r"(r[1]), "=r"(r[2]), "=r"(r[3]) : "r"(a));
}
// fp32-accumulate MMA
__device__ __forceinline__ void mma16816(float* c, const uint32_t* a,
                                         uint32_t b0, uint32_t b1) {
    asm volatile("mma.sync.aligned.m16n8k16.row.col.f32.f16.f16.f32 "
                 "{%0,%1,%2,%3},{%4,%5,%6,%7},{%8,%9},{%0,%1,%2,%3};"
                 : "+f"(c[0]), "+f"(c[1]), "+f"(c[2]), "+f"(c[3])
                 : "r"(a[0]), "r"(a[1]), "r"(a[2]), "r"(a[3]), "r"(b0), "r"(b1));
}
// fp16-accumulate MMA (2 half2 regs: [0]=rows r cols{c0,c1}, [1]=rows r+8)
__device__ __forceinline__ void mma16816_h(uint32_t* c, const uint32_t* a,
                                           uint32_t b0, uint32_t b1) {
    asm volatile("mma.sync.aligned.m16n8k16.row.col.f16.f16.f16.f16 "
                 "{%0,%1},{%2,%3,%4,%5},{%6,%7},{%0,%1};"
                 : "+r"(c[0]), "+r"(c[1])
                 : "r"(a[0]), "r"(a[1]), "r"(a[2]), "r"(a[3]), "r"(b0), "r"(b1));
}
__device__ __forceinline__ uint32_t packh2(float a, float b) {
    __half2 h = __halves2half2(__float2half_rn(a), __float2half_rn(b));
    return *(uint32_t*)&h;
}

// ============================================================
// PE table
// ============================================================
__global__ void pe_kernel(float* __restrict__ pe) {
    int id = blockIdx.x * blockDim.x + threadIdx.x;
    int pos = id >> 8, i = id & 255;
    const float c = (float)(-9.210340371976184 / 512.0);
    float div = expf((float)(2 * i) * c);
    float ang = (float)pos * div;
    float s, co;
    sincosf(ang, &s, &co);
    pe[pos * Dm + i] = s;
    pe[pos * Dm + i + 256] = co;
}

// ============================================================
// Embedding + PE add (pure bandwidth, float4)
// ============================================================
__global__ void embed_kernel(const int* __restrict__ inputs,
                             const float* __restrict__ embed,
                             const float* __restrict__ pe,
                             float* __restrict__ x) {
    size_t q = (size_t)blockIdx.x * blockDim.x + threadIdx.x;
    int token = (int)(q >> 7);
    int c4 = (int)(q & 127);
    int pos = token & (Tt - 1);
    int tok = inputs[token];
    float4 e = ((const float4*)(embed + (size_t)tok * Dm))[c4];
    float4 p = ((const float4*)(pe + (size_t)pos * Dm))[c4];
    ((float4*)(x + (size_t)token * Dm))[c4] =
        make_float4(e.x + p.x, e.y + p.y, e.z + p.z, e.w + p.w);
}

// ============================================================
// Fused weight prep (one launch): fp32 [K][N] -> fp16 [N][K]
// ============================================================
__global__ void wprep_all(const float* __restrict__ wq, const float* __restrict__ wk,
                          const float* __restrict__ wv, const float* __restrict__ wo,
                          const float* __restrict__ w1, const float* __restrict__ w2,
                          __half* __restrict__ wh) {
    __shared__ float tt[32][33];
    int t = blockIdx.x;
    const float* src;
    __half* dh;
    int srcN, dstK, n0, k0, nd;

    if (t < 4608) {
        int g = t / 1536, r = t % 1536;
        int l = r >> 8, rr = r & 255;
        n0 = (rr & 15) << 5; k0 = (rr >> 4) << 5;
        const float* w = (g == 0) ? wq : (g == 1) ? wk : wv;
        src = w + (size_t)l * WSZP;
        dh = wh + OFF_QKV + (size_t)l * SZ_QKV;
        srcN = 512; dstK = 512; nd = g * 512 + n0;
    } else if (t < 6144) {
        int r = t - 4608;
        int l = r >> 8, rr = r & 255;
        n0 = (rr & 15) << 5; k0 = (rr >> 4) << 5;
        src = wo + (size_t)l * WSZP;
        dh = wh + OFF_WO + (size_t)l * WSZP;
        srcN = 512; dstK = 512; nd = n0;
    } else if (t < 12288) {
        int r = t - 6144;
        int l = r >> 10, rr = r & 1023;
        n0 = (rr & 63) << 5; k0 = (rr >> 6) << 5;
        src = w1 + (size_t)l * WSZM;
        dh = wh + OFF_W1 + (size_t)l * WSZM;
        srcN = 2048; dstK = 512; nd = n0;
    } else {
        int r = t - 12288;
        int l = r >> 10, rr = r & 1023;
        n0 = (rr & 15) << 5; k0 = (rr >> 4) << 5;
        src = w2 + (size_t)l * WSZM;
        dh = wh + OFF_W2 + (size_t)l * WSZM;
        srcN = 512; dstK = 2048; nd = n0;
    }

    int tx = threadIdx.x, ty = threadIdx.y;
#pragma unroll
    for (int i = 0; i < 4; i++)
        tt[ty + i * 8][tx] = src[(size_t)(k0 + ty + i * 8) * srcN + n0 + tx];
    __syncthreads();
#pragma unroll
    for (int i = 0; i < 4; i++) {
        float v = tt[tx][ty + i * 8];
        dh[(size_t)(nd + ty + i * 8) * dstK + k0 + tx] = __float2half_rn(v);
    }
}

// ============================================================
// LayerNorm — float4 vectorized; 128 threads per token
// ============================================================
template <bool WHF>
__global__ void ln_kernel(const float* __restrict__ x,
                          const float* __restrict__ sc,
                          const float* __restrict__ bi,
                          float* __restrict__ outf,
                          __half* __restrict__ oh) {
    __shared__ float red[4];
    int t = blockIdx.x;
    int tid = threadIdx.x;
    float4 v = ((const float4*)(x + (size_t)t * Dm))[tid];

    float sum = v.x + v.y + v.z + v.w;
#pragma unroll
    for (int o = 16; o; o >>= 1) sum += __shfl_xor_sync(0xffffffffu, sum, o);
    if ((tid & 31) == 0) red[tid >> 5] = sum;
    __syncthreads();
    float mean = (red[0] + red[1] + red[2] + red[3]) * (1.f / Dm);
    __syncthreads();

    float dx = v.x - mean, dy = v.y - mean, dz = v.z - mean, dw = v.w - mean;
    float sq = dx * dx + dy * dy + dz * dz + dw * dw;
#pragma unroll
    for (int o = 16; o; o >>= 1) sq += __shfl_xor_sync(0xffffffffu, sq, o);
    if ((tid & 31) == 0) red[tid >> 5] = sq;
    __syncthreads();
    float var = (red[0] + red[1] + red[2] + red[3]) * (1.f / Dm);
    float rstd = rsqrtf(var + 1e-6f);

    float4 s4 = ((const float4*)sc)[tid];
    float4 b4 = ((const float4*)bi)[tid];
    float y0 = dx * rstd * s4.x + b4.x;
    float y1 = dy * rstd * s4.y + b4.y;
    float y2 = dz * rstd * s4.z + b4.z;
    float y3 = dw * rstd * s4.w + b4.w;

    if (WHF) {
        uint2 o2;
        o2.x = packh2(y0, y1);
        o2.y = packh2(y2, y3);
        ((uint2*)(oh + (size_t)t * Dm))[tid] = o2;
    } else {
        ((float4*)(outf + (size_t)t * Dm))[tid] = make_float4(y0, y1, y2, y3);
    }
}

// ============================================================
// HMMA fp16 GEMM: C[M,N] (+)= A[M,K] @ B[N,K]^T
// F16A: fp16 accumulator (tests fp32-acc half-rate hypothesis;
//       used only for K=512 GEMMs — error budget)
// CTA 128x128, 8 warps, warp tile 32x64, K-chunk 64,
// 3-stage cp.async (32KB/stage), one sync per chunk.
// ============================================================
#define ST_B    16384
#define STAGE   32768
#define SMEM_GEMM (3 * STAGE)

template <bool F16A, bool ACCUM, bool RELU, bool BIAS, bool WF32, bool WHF>
__global__ void __launch_bounds__(256, 2)
hgemm(const __half* __restrict__ A, const __half* __restrict__ B,
      const float* __restrict__ bias, float* __restrict__ C,
      __half* __restrict__ O,
      int N, int K) {
    extern __shared__ char smem[];
    uint32_t sb = smem_u32(smem);
    int tid = threadIdx.x, wid = tid >> 5, lane = tid & 31;
    int m0 = blockIdx.y * 128, n0 = blockIdx.x * 128;
    int wm = (wid >> 1) * 32, wn = (wid & 1) * 64;

    float accf[2][8][4];
    uint32_t acch[2][8][2];
    if (F16A) {
#pragma unroll
        for (int i = 0; i < 2; i++)
#pragma unroll
            for (int j = 0; j < 8; j++) { acch[i][j][0] = 0u; acch[i][j][1] = 0u; }
    } else {
#pragma unroll
        for (int i = 0; i < 2; i++)
#pragma unroll
            for (int j = 0; j < 8; j++)
#pragma unroll
                for (int e = 0; e < 4; e++) accf[i][j][e] = 0.f;
    }

    const int NC = K >> 6;

#define LOAD_CHUNK(c, s) do {                                                   \
    int kt = (c) << 6;                                                          \
    uint32_t st_ = sb + (s) * STAGE;                                            \
    _Pragma("unroll")                                                           \
    for (int i = 0; i < 4; i++) {                                               \
        int u = tid + i * 256;                                                  \
        int row = u >> 3, kc = u & 7;                                           \
        uint32_t so = SWZ((uint32_t)(row * 128 + kc * 16));                     \
        size_t ga = (size_t)(m0 + row) * K + kt + kc * 8;                       \
        size_t gb = (size_t)(n0 + row) * K + kt + kc * 8;                       \
        CP16(st_ + so,        A + ga);                                          \
        CP16(st_ + ST_B + so, B + gb);                                          \
    } } while (0)

    LOAD_CHUNK(0, 0);
    CP_COMMIT();
    LOAD_CHUNK(1, 1);
    CP_COMMIT();

    for (int c = 0; c < NC; c++) {
        if (c + 1 < NC) { CP_WAIT(1); } else { CP_WAIT(0); }
        __syncthreads();
        if (c + 2 < NC) {
            LOAD_CHUNK(c + 2, (c + 2) % 3);
            CP_COMMIT();
        }
        uint32_t st = sb + (c % 3) * STAGE;

#pragma unroll
        for (int ks = 0; ks < 4; ks++) {
            int kb = ks * 32 + ((lane >> 4) & 1) * 16;
            uint32_t ah[2][4];
#pragma unroll
            for (int mf = 0; mf < 2; mf++) {
                uint32_t ro = (uint32_t)((wm + mf * 16 + (lane & 15)) * 128 + kb);
                ldsm4(ah[mf], st + SWZ(ro));
            }
#pragma unroll
            for (int nf = 0; nf < 4; nf++) {
                uint32_t bh[4];
                uint32_t ro = (uint32_t)((wn + nf * 16 + (lane & 15)) * 128 + kb);
                ldsm4(bh, st + ST_B + SWZ(ro));
#pragma unroll
                for (int mf = 0; mf < 2; mf++)
#pragma unroll
                    for (int sl = 0; sl < 2; sl++) {
                        if (F16A)
                            mma16816_h(acch[mf][nf * 2 + sl], ah[mf], bh[sl], bh[sl + 2]);
                        else
                            mma16816(accf[mf][nf * 2 + sl], ah[mf], bh[sl], bh[sl + 2]);
                    }
            }
        }
    }

    // epilogue
    int r0 = m0 + wm + (lane >> 2);
    int cb = n0 + wn + (lane & 3) * 2;
#pragma unroll
    for (int mf = 0; mf < 2; mf++)
#pragma unroll
        for (int hf = 0; hf < 2; hf++) {
            int rr = r0 + mf * 16 + hf * 8;
#pragma unroll
            for (int nb = 0; nb < 8; nb++) {
                int cc = cb + nb * 8;
                // fast path: fp16 acc, no bias/relu/accum, fp16 out -> direct store
                if (F16A && WHF && !BIAS && !RELU && !ACCUM) {
                    *(uint32_t*)(O + (size_t)rr * N + cc) = acch[mf][nb][hf];
                    continue;
                }
                float v0, v1;
                if (F16A) {
                    __half2 hv = *(__half2*)&acch[mf][nb][hf];
                    v0 = __low2float(hv);
                    v1 = __high2float(hv);
                } else {
                    v0 = accf[mf][nb][hf * 2 + 0];
                    v1 = accf[mf][nb][hf * 2 + 1];
                }
                if (BIAS) {
                    float2 bv = *(const float2*)(bias + cc);
                    v0 += bv.x; v1 += bv.y;
                }
                if (RELU) { v0 = fmaxf(v0, 0.f); v1 = fmaxf(v1, 0.f); }
                if (ACCUM) {
                    atomicAdd(C + (size_t)rr * N + cc, v0);
                    atomicAdd(C + (size_t)rr * N + cc + 1, v1);
                } else if (WF32) {
                    *(float2*)(C + (size_t)rr * N + cc) = make_float2(v0, v1);
                }
                if (WHF)
                    *(__half2*)(O + (size_t)rr * N + cc) =
                        __halves2half2(__float2half_rn(v0), __float2half_rn(v1));
            }
        }
}

// ============================================================
// Tensor-core local block attention.
// ============================================================
#define AS_Q  0
#define AS_K  8192
#define AS_VT 16384
#define AS_MK 24576

__global__ void __launch_bounds__(128)
attn_mma(const __half* __restrict__ qkvh,
         const int* __restrict__ inputs,
         __half* __restrict__ aout,
         int lp) {
    __shared__ __align__(16) char smem[24576 + 256];
    uint32_t sb = smem_u32(smem);
    float* maskS = (float*)(smem + AS_MK);

    int n = blockIdx.x, h = blockIdx.y, b = blockIdx.z;
    int tid = threadIdx.x, wid = tid >> 5, lane = tid & 31;
    int base = n * 64 - lp;

#pragma unroll
    for (int i = 0; i < 4; i++) {
        int u = tid + i * 128;
        int row = u >> 3, c = u & 7;
        int gt = base + row;
        uint4 qv = make_uint4(0, 0, 0, 0), kv = qv, vv = qv;
        if (gt >= 0 && gt < Tt) {
            const __half* p = qkvh + ((size_t)(b * Tt + gt)) * 1536 + h * HDm;
            qv = *(const uint4*)(p + c * 8);
            kv = *(const uint4*)(p + 512 + c * 8);
            vv = *(const uint4*)(p + 1024 + c * 8);
        }
        uint32_t so = SWZ((uint32_t)(row * 128 + c * 16));
        *(uint4*)(smem + AS_Q + so) = qv;
        *(uint4*)(smem + AS_K + so) = kv;
        __half vh[8];
        *(uint4*)vh = vv;
#pragma unroll
        for (int j = 0; j < 8; j++) {
            uint32_t off = (uint32_t)((c * 8 + j) * 128 + row * 2);
            *(__half*)(smem + AS_VT + SWZ(off)) = vh[j];
        }
    }
    if (tid < 64) {
        int gt = base + tid;
        maskS[tid] = (gt >= 0 && gt < Tt && inputs[b * Tt + gt] > 0) ? 1.f : 0.f;
    }
    __syncthreads();

    int wm = wid * 16;

    float s[8][4];
#pragma unroll
    for (int j = 0; j < 8; j++)
#pragma unroll
        for (int e = 0; e < 4; e++) s[j][e] = 0.f;

#pragma unroll
    for (int ks = 0; ks < 4; ks++) {
        int kb = ks * 32 + ((lane >> 4) & 1) * 16;
        uint32_t a[4];
        ldsm4(a, sb + AS_Q + SWZ((uint32_t)((wm + (lane & 15)) * 128 + kb)));
#pragma unroll
        for (int nf = 0; nf < 4; nf++) {
            uint32_t bh[4];
            ldsm4(bh, sb + AS_K + SWZ((uint32_t)((nf * 16 + (lane & 15)) * 128 + kb)));
            mma16816(s[nf * 2 + 0], a, bh[0], bh[2]);
            mma16816(s[nf * 2 + 1], a, bh[1], bh[3]);
        }
    }

#pragma unroll
    for (int j = 0; j < 8; j++) {
        int col = j * 8 + (lane & 3) * 2;
        float m0 = maskS[col], m1 = maskS[col + 1];
        s[j][0] = (m0 > 0.f) ? s[j][0] * 0.125f : -1e9f;
        s[j][2] = (m0 > 0.f) ? s[j][2] * 0.125f : -1e9f;
        s[j][1] = (m1 > 0.f) ? s[j][1] * 0.125f : -1e9f;
        s[j][3] = (m1 > 0.f) ? s[j][3] * 0.125f : -1e9f;
    }

    float mx0 = -1e30f, mx1 = -1e30f;
#pragma unroll
    for (int j = 0; j < 8; j++) {
        mx0 = fmaxf(mx0, fmaxf(s[j][0], s[j][1]));
        mx1 = fmaxf(mx1, fmaxf(s[j][2], s[j][3]));
    }
    mx0 = fmaxf(mx0, __shfl_xor_sync(0xffffffffu, mx0, 1));
    mx0 = fmaxf(mx0, __shfl_xor_sync(0xffffffffu, mx0, 2));
    mx1 = fmaxf(mx1, __shfl_xor_sync(0xffffffffu, mx1, 1));
    mx1 = fmaxf(mx1, __shfl_xor_sync(0xffffffffu, mx1, 2));

    float sm0 = 0.f, sm1 = 0.f;
#pragma unroll
    for (int j = 0; j < 8; j++) {
        s[j][0] = expf(s[j][0] - mx0); sm0 += s[j][0];
        s[j][1] = expf(s[j][1] - mx0); sm0 += s[j][1];
        s[j][2] = expf(s[j][2] - mx1); sm1 += s[j][2];
        s[j][3] = expf(s[j][3] - mx1); sm1 += s[j][3];
    }
    sm0 += __shfl_xor_sync(0xffffffffu, sm0, 1);
    sm0 += __shfl_xor_sync(0xffffffffu, sm0, 2);
    sm1 += __shfl_xor_sync(0xffffffffu, sm1, 1);
    sm1 += __shfl_xor_sync(0xffffffffu, sm1, 2);
    float inv0 = 1.f / sm0, inv1 = 1.f / sm1;

    float o[8][4];
#pragma unroll
    for (int j = 0; j < 8; j++)
#pragma unroll
        for (int e = 0; e < 4; e++) o[j][e] = 0.f;

#pragma unroll
    for (int kk = 0; kk < 4; kk++) {
        uint32_t a[4];
        a[0] = packh2(s[2 * kk][0] * inv0, s[2 * kk][1] * inv0);
        a[1] = packh2(s[2 * kk][2] * inv1, s[2 * kk][3] * inv1);
        a[2] = packh2(s[2 * kk + 1][0] * inv0, s[2 * kk + 1][1] * inv0);
        a[3] = packh2(s[2 * kk + 1][2] * inv1, s[2 * kk + 1][3] * inv1);
        int kb = kk * 32 + ((lane >> 4) & 1) * 16;
#pragma unroll
        for (int nf = 0; nf < 4; nf++) {
            uint32_t bh[4];
            ldsm4(bh, sb + AS_VT + SWZ((uint32_t)((nf * 16 + (lane & 15)) * 128 + kb)));
            mma16816(o[nf * 2 + 0], a, bh[0], bh[2]);
            mma16816(o[nf * 2 + 1], a, bh[1], bh[3]);
        }
    }

    int r0 = base + wm + (lane >> 2);
    int r1 = r0 + 8;
#pragma unroll
    for (int j = 0; j < 8; j++) {
        int col = j * 8 + (lane & 3) * 2;
        if (r0 >= 0 && r0 < Tt)
            *(__half2*)(aout + ((size_t)(b * Tt + r0)) * Dm + h * HDm + col) =
                __halves2half2(__float2half_rn(o[j][0]), __float2half_rn(o[j][1]));
        if (r1 >= 0 && r1 < Tt)
            *(__half2*)(aout + ((size_t)(b * Tt + r1)) * Dm + h * HDm + col) =
                __halves2half2(__float2half_rn(o[j][2]), __float2half_rn(o[j][3]));
    }
}

// ============================================================
// Host driver
// ============================================================
extern "C" void kernel_launch(void* const* d_in, const int* in_sizes, int n_in,
                              void* d_out, int out_size) {
    const int*   inputs = (const int*)  d_in[0];
    const float* embed  = (const float*)d_in[1];
    const float* wq     = (const float*)d_in[2];
    const float* wk     = (const float*)d_in[3];
    const float* wv     = (const float*)d_in[4];
    const float* wo     = (const float*)d_in[5];
    const float* ln1_s  = (const float*)d_in[6];
    const float* ln1_b  = (const float*)d_in[7];
    const float* ln2_s  = (const float*)d_in[8];
    const float* ln2_b  = (const float*)d_in[9];
    const float* w1     = (const float*)d_in[10];
    const float* b1     = (const float*)d_in[11];
    const float* w2     = (const float*)d_in[12];
    const float* b2     = (const float*)d_in[13];
    const float* lnf_s  = (const float*)d_in[14];
    const float* lnf_b  = (const float*)d_in[15];

    float *x, *pe;
    __half *qkvh, *h, *a, *m, *wh;
    cudaGetSymbolAddress((void**)&x,    g_x);
    cudaGetSymbolAddress((void**)&pe,   g_pe);
    cudaGetSymbolAddress((void**)&qkvh, g_qkvh);
    cudaGetSymbolAddress((void**)&h,    g_h);
    cudaGetSymbolAddress((void**)&a,    g_a);
    cudaGetSymbolAddress((void**)&m,    g_m);
    cudaGetSymbolAddress((void**)&wh,   g_wh);

    // QKV: f16-acc, direct fp16 store
    cudaFuncSetAttribute(hgemm<true, false,false,false,false,true>, cudaFuncAttributeMaxDynamicSharedMemorySize, SMEM_GEMM);
    // WO: f16-acc, atomic accumulate into fp32 x
    cudaFuncSetAttribute(hgemm<true, true, false,false,true, false>, cudaFuncAttributeMaxDynamicSharedMemorySize, SMEM_GEMM);
    // MLP1: f16-acc, bias+relu, fp16 out
    cudaFuncSetAttribute(hgemm<true, false,true, true, false,true>, cudaFuncAttributeMaxDynamicSharedMemorySize, SMEM_GEMM);
    // MLP2: f32-acc (K=2048), bias, atomic accumulate
    cudaFuncSetAttribute(hgemm<false,true, false,true, true, false>, cudaFuncAttributeMaxDynamicSharedMemorySize, SMEM_GEMM);

    wprep_all<<<18432, dim3(32, 8)>>>(wq, wk, wv, wo, w1, w2, wh);
    pe_kernel<<<(Tt * 256) / 256, 256>>>(pe);
    embed_kernel<<<(TOK * Dm / 4) / 256, 256>>>(inputs, embed, pe, x);

    dim3 gQKV(1536 / 128, TOK / 128);
    dim3 gP(Dm / 128, TOK / 128);
    dim3 gM1(MLPD / 128, TOK / 128);

    for (int l = 0; l < Lnum; l++) {
        int lp = (l & 1) ? 32 : 0;
        int nb = (l & 1) ? (Tt + 64) / 64 : Tt / 64;

        ln_kernel<true><<<TOK, 128>>>(x, ln1_s + l * Dm, ln1_b + l * Dm,
                                      nullptr, h);

        // qkv (fp16) = h @ [wq|wk|wv]   (fp16 accum, direct store)
        hgemm<true,false,false,false,false,true><<<gQKV, 256, SMEM_GEMM>>>(
            h, wh + OFF_QKV + (size_t)l * SZ_QKV,
            nullptr, nullptr, qkvh, 1536, Dm);

        attn_mma<<<dim3(nb, Hh, Bb), 128>>>(qkvh, inputs, a, lp);

        // x += attn @ wo   (fp16 accum, atomic epilogue)
        hgemm<true,true,false,false,true,false><<<gP, 256, SMEM_GEMM>>>(
            a, wh + OFF_WO + (size_t)l * WSZP,
            nullptr, x, nullptr, Dm, Dm);

        ln_kernel<true><<<TOK, 128>>>(x, ln2_s + l * Dm, ln2_b + l * Dm,
                                      nullptr, h);

        // m = relu(h @ w1 + b1)  (fp16 accum, fp16 out)
        hgemm<true,false,true,true,false,true><<<gM1, 256, SMEM_GEMM>>>(
            h, wh + OFF_W1 + (size_t)l * WSZM,
            b1 + (size_t)l * MLPD, nullptr, m, MLPD, Dm);

        // x += m @ w2 + b2   (fp32 accum — K=2048, atomic epilogue)
        hgemm<false,true,false,true,true,false><<<gP, 256, SMEM_GEMM>>>(
            m, wh + OFF_W2 + (size_t)l * WSZM,
            b2 + (size_t)l * Dm, x, nullptr, Dm, MLPD);
    }

    ln_kernel<false><<<TOK, 128>>>(x, lnf_s, lnf_b, (float*)d_out, nullptr);
}